// round 1
// baseline (speedup 1.0000x reference)
#include <cuda_runtime.h>
#include <cuda_bf16.h>
#include <math.h>

// Problem constants
#define BB      2
#define SS      2048
#define DM      4096
#define NH      32
#define NKV     8
#define HD      128
#define QKVD    6144          // (32 + 2*8) * 128
#define MROWS   4096          // B*S

// Scratch (allocation-free rule: __device__ globals)
__device__ float g_qkv [(size_t)MROWS * QKVD];   // qkv projection output (RoPE applied in place)
__device__ float g_attn[(size_t)MROWS * DM];     // attention output, [b*s, h*d]

// ---------------------------------------------------------------------------
// GEMM: C[M,N] = A[M,K] @ B[K,N], all row-major fp32.
// 128x128 block tile, BK=16, 256 threads, 8x8 per thread, register prefetch.
// ---------------------------------------------------------------------------
#define GBM 128
#define GBN 128
#define GBK 16

__global__ __launch_bounds__(256, 1) void sgemm_k(
    const float* __restrict__ A, const float* __restrict__ B,
    float* __restrict__ C, int M, int N, int K)
{
    __shared__ __align__(16) float As[GBK][GBM + 4];   // transposed, padded
    __shared__ __align__(16) float Bs[GBK][GBN];

    const int tid  = threadIdx.x;
    const int bm   = blockIdx.y * GBM;
    const int bn   = blockIdx.x * GBN;
    const int tx   = tid & 15;
    const int ty   = tid >> 4;
    const int row0 = ty * 8;
    const int col0 = tx * 8;

    const int a_m = tid >> 2;          // 0..63
    const int a_k = (tid & 3) << 2;    // 0,4,8,12
    const int b_k = tid >> 5;          // 0..7
    const int b_n = (tid & 31) << 2;   // 0..124

    const float* Ap = A + (size_t)bm * K;
    const float* Bp = B + bn;

    float4 ar0 = *(const float4*)(Ap + (size_t)a_m * K + a_k);
    float4 ar1 = *(const float4*)(Ap + (size_t)(a_m + 64) * K + a_k);
    float4 br0 = *(const float4*)(Bp + (size_t)b_k * N + b_n);
    float4 br1 = *(const float4*)(Bp + (size_t)(b_k + 8) * N + b_n);

    float acc[8][8];
    #pragma unroll
    for (int i = 0; i < 8; i++)
        #pragma unroll
        for (int j = 0; j < 8; j++) acc[i][j] = 0.f;

    const int ktiles = K / GBK;
    for (int kt = 0; kt < ktiles; kt++) {
        As[a_k + 0][a_m]      = ar0.x;
        As[a_k + 1][a_m]      = ar0.y;
        As[a_k + 2][a_m]      = ar0.z;
        As[a_k + 3][a_m]      = ar0.w;
        As[a_k + 0][a_m + 64] = ar1.x;
        As[a_k + 1][a_m + 64] = ar1.y;
        As[a_k + 2][a_m + 64] = ar1.z;
        As[a_k + 3][a_m + 64] = ar1.w;
        *(float4*)&Bs[b_k][b_n]     = br0;
        *(float4*)&Bs[b_k + 8][b_n] = br1;
        __syncthreads();

        if (kt + 1 < ktiles) {     // register prefetch of next tile
            const float* An = Ap + (kt + 1) * GBK;
            const float* Bn = Bp + (size_t)(kt + 1) * GBK * N;
            ar0 = *(const float4*)(An + (size_t)a_m * K + a_k);
            ar1 = *(const float4*)(An + (size_t)(a_m + 64) * K + a_k);
            br0 = *(const float4*)(Bn + (size_t)b_k * N + b_n);
            br1 = *(const float4*)(Bn + (size_t)(b_k + 8) * N + b_n);
        }

        #pragma unroll
        for (int k = 0; k < GBK; k++) {
            float a_r[8], b_r[8];
            *(float4*)&a_r[0] = *(float4*)&As[k][row0];
            *(float4*)&a_r[4] = *(float4*)&As[k][row0 + 4];
            *(float4*)&b_r[0] = *(float4*)&Bs[k][col0];
            *(float4*)&b_r[4] = *(float4*)&Bs[k][col0 + 4];
            #pragma unroll
            for (int i = 0; i < 8; i++)
                #pragma unroll
                for (int j = 0; j < 8; j++)
                    acc[i][j] = fmaf(a_r[i], b_r[j], acc[i][j]);
        }
        __syncthreads();
    }

    #pragma unroll
    for (int i = 0; i < 8; i++) {
        float* Cp = C + (size_t)(bm + row0 + i) * N + bn + col0;
        *(float4*)(Cp)     = make_float4(acc[i][0], acc[i][1], acc[i][2], acc[i][3]);
        *(float4*)(Cp + 4) = make_float4(acc[i][4], acc[i][5], acc[i][6], acc[i][7]);
    }
}

// ---------------------------------------------------------------------------
// RoPE in place on Q (cols 0..4095) and K (cols 4096..5119) of g_qkv.
// cos/sin tables are [S,128] with halves duplicated: cos[s,d] == cos[s,d+64].
// out[d]    = x[d]*c - x[d+64]*s
// out[d+64] = x[d+64]*c + x[d]*s        (d < 64)
// ---------------------------------------------------------------------------
__global__ void rope_k(const float* __restrict__ cost, const float* __restrict__ sint)
{
    const int row = blockIdx.x;            // 0..4095
    const int s   = row & (SS - 1);        // position within its batch
    float* q = g_qkv + (size_t)row * QKVD;

    for (int p = threadIdx.x; p < (NH + NKV) * 64; p += blockDim.x) {
        const int h = p >> 6;              // 0..39
        const int d = p & 63;
        const int base = (h < NH) ? h * HD : NH * HD + (h - NH) * HD;
        const float c  = cost[s * HD + d];
        const float sn = sint[s * HD + d];
        const float x1 = q[base + d];
        const float x2 = q[base + d + 64];
        q[base + d]      = x1 * c - x2 * sn;
        q[base + d + 64] = x2 * c + x1 * sn;
    }
}

// ---------------------------------------------------------------------------
// Flash attention, causal, fp32.  One CTA per (q-tile of 64, head, batch).
// Smem layouts transposed so both GEMM phases use contiguous LDS.128.
// ---------------------------------------------------------------------------
#define AT_BM   64
#define AT_BN   64
#define QT_P    68            // padded pitch for Qt/Kt/St rows (16B aligned, low conflicts)
#define SM_QT   0
#define SM_KT   (HD * QT_P)                   // 8704
#define SM_VS   (SM_KT + HD * QT_P)           // 17408
#define SM_ST   (SM_VS + AT_BN * HD)          // 25600
#define ATTN_SMEM_FLOATS (SM_ST + AT_BN * QT_P)   // 29952
#define ATTN_SMEM_BYTES  (ATTN_SMEM_FLOATS * 4)   // 119808

__global__ __launch_bounds__(256, 1) void attn_k()
{
    extern __shared__ __align__(16) float sm[];
    float* Qt = sm + SM_QT;   // [d][query], pitch QT_P
    float* Kt = sm + SM_KT;   // [d][key],   pitch QT_P
    float* Vs = sm + SM_VS;   // [key][d],   pitch 128
    float* St = sm + SM_ST;   // [key][query], pitch QT_P (transposed probs)

    const int qt  = blockIdx.x;           // q tile 0..31
    const int qh  = blockIdx.y;           // query head
    const int b   = blockIdx.z;
    const int kh  = qh >> 2;              // kv head (N_GROUPS = 4)
    const int tid = threadIdx.x;
    const int rg  = tid >> 4;             // 0..15 row group (4 rows)
    const int cg  = tid & 15;             // 0..15 col group

    const float* Qg = g_qkv + (size_t)(b * SS + qt * AT_BM) * QKVD + qh * HD;
    const float* Kg = g_qkv + (size_t)(b * SS) * QKVD + NH * HD + kh * HD;
    const float* Vg = g_qkv + (size_t)(b * SS) * QKVD + (NH + NKV) * HD + kh * HD;

    const float scale = 0.08838834764831845f;   // 1/sqrt(128)

    // Load Q transposed, pre-scaled
    for (int idx = tid; idx < AT_BM * HD; idx += 256) {
        const int r = idx >> 7, d = idx & 127;
        Qt[d * QT_P + r] = Qg[(size_t)r * QKVD + d] * scale;
    }

    float o[4][8];
    #pragma unroll
    for (int i = 0; i < 4; i++)
        #pragma unroll
        for (int j = 0; j < 8; j++) o[i][j] = 0.f;
    float m_r[4] = {-1e30f, -1e30f, -1e30f, -1e30f};
    float l_r[4] = {0.f, 0.f, 0.f, 0.f};

    for (int kt2 = 0; kt2 <= qt; kt2++) {
        __syncthreads();   // protect Kt/Vs/St from previous iteration's readers

        // Load K (transposed) and V tiles
        for (int idx = tid; idx < AT_BN * HD; idx += 256) {
            const int p = idx >> 7, d = idx & 127;
            const size_t grow = (size_t)(kt2 * AT_BN + p) * QKVD;
            Kt[d * QT_P + p] = Kg[grow + d];
            Vs[p * HD + d]   = Vg[grow + d];
        }
        __syncthreads();

        // S = Q K^T (4x4 micro-tile per thread)
        float sv[4][4];
        #pragma unroll
        for (int i = 0; i < 4; i++)
            #pragma unroll
            for (int j = 0; j < 4; j++) sv[i][j] = 0.f;

        #pragma unroll 4
        for (int d = 0; d < HD; d++) {
            const float4 qv = *(const float4*)&Qt[d * QT_P + 4 * rg];
            const float4 kv = *(const float4*)&Kt[d * QT_P + 4 * cg];
            const float qa[4] = {qv.x, qv.y, qv.z, qv.w};
            const float ka[4] = {kv.x, kv.y, kv.z, kv.w};
            #pragma unroll
            for (int i = 0; i < 4; i++)
                #pragma unroll
                for (int j = 0; j < 4; j++)
                    sv[i][j] = fmaf(qa[i], ka[j], sv[i][j]);
        }

        // Causal mask (only the diagonal tile needs it)
        if (kt2 == qt) {
            #pragma unroll
            for (int i = 0; i < 4; i++)
                #pragma unroll
                for (int j = 0; j < 4; j++)
                    if (4 * cg + j > 4 * rg + i) sv[i][j] = -1e30f;
        }

        // Online softmax: m/l replicated across the 16 threads owning each row
        float scl[4];
        #pragma unroll
        for (int i = 0; i < 4; i++) {
            float mx = fmaxf(fmaxf(sv[i][0], sv[i][1]), fmaxf(sv[i][2], sv[i][3]));
            #pragma unroll
            for (int off = 1; off < 16; off <<= 1)
                mx = fmaxf(mx, __shfl_xor_sync(0xffffffffu, mx, off));
            const float mnew = fmaxf(m_r[i], mx);
            scl[i] = __expf(m_r[i] - mnew);
            m_r[i] = mnew;
            float rs = 0.f;
            #pragma unroll
            for (int j = 0; j < 4; j++) {
                const float p = __expf(sv[i][j] - mnew);
                sv[i][j] = p;
                rs += p;
            }
            #pragma unroll
            for (int off = 1; off < 16; off <<= 1)
                rs += __shfl_xor_sync(0xffffffffu, rs, off);
            l_r[i] = l_r[i] * scl[i] + rs;
        }

        // Rescale accumulators
        #pragma unroll
        for (int i = 0; i < 4; i++)
            #pragma unroll
            for (int j = 0; j < 8; j++) o[i][j] *= scl[i];

        // Store probs transposed: St[key][query]
        #pragma unroll
        for (int j = 0; j < 4; j++) {
            *(float4*)&St[(4 * cg + j) * QT_P + 4 * rg] =
                make_float4(sv[0][j], sv[1][j], sv[2][j], sv[3][j]);
        }
        __syncthreads();

        // O += P V   (4 rows x 8 cols per thread)
        #pragma unroll 2
        for (int p = 0; p < AT_BN; p++) {
            const float4 pr = *(const float4*)&St[p * QT_P + 4 * rg];
            const float4 v0 = *(const float4*)&Vs[p * HD + 8 * cg];
            const float4 v1 = *(const float4*)&Vs[p * HD + 8 * cg + 4];
            const float pa[4] = {pr.x, pr.y, pr.z, pr.w};
            const float va[8] = {v0.x, v0.y, v0.z, v0.w, v1.x, v1.y, v1.z, v1.w};
            #pragma unroll
            for (int i = 0; i < 4; i++)
                #pragma unroll
                for (int j = 0; j < 8; j++)
                    o[i][j] = fmaf(pa[i], va[j], o[i][j]);
        }
    }

    // Normalize and write out: g_attn[b*s + q][qh*128 + c]
    float* Og = g_attn + (size_t)(b * SS + qt * AT_BM) * DM + qh * HD;
    #pragma unroll
    for (int i = 0; i < 4; i++) {
        const float inv = 1.f / l_r[i];
        float* dst = Og + (size_t)(4 * rg + i) * DM + 8 * cg;
        *(float4*)(dst)     = make_float4(o[i][0] * inv, o[i][1] * inv,
                                          o[i][2] * inv, o[i][3] * inv);
        *(float4*)(dst + 4) = make_float4(o[i][4] * inv, o[i][5] * inv,
                                          o[i][6] * inv, o[i][7] * inv);
    }
}

// ---------------------------------------------------------------------------
// Launch
// ---------------------------------------------------------------------------
extern "C" void kernel_launch(void* const* d_in, const int* in_sizes, int n_in,
                              void* d_out, int out_size)
{
    const float* hs   = (const float*)d_in[0];   // (B,S,4096) fp32
    const float* cosb = (const float*)d_in[1];   // (S,128)
    const float* sinb = (const float*)d_in[2];   // (S,128)
    const float* Wqkv = (const float*)d_in[3];   // (4096,6144)
    const float* Wout = (const float*)d_in[4];   // (4096,4096)
    float* out = (float*)d_out;                  // (B,S,4096)

    float* qkv_ptr;
    float* attn_ptr;
    cudaGetSymbolAddress((void**)&qkv_ptr,  g_qkv);
    cudaGetSymbolAddress((void**)&attn_ptr, g_attn);

    cudaFuncSetAttribute(attn_k, cudaFuncAttributeMaxDynamicSharedMemorySize,
                         ATTN_SMEM_BYTES);

    // 1) QKV projection
    sgemm_k<<<dim3(QKVD / GBN, MROWS / GBM), 256>>>(hs, Wqkv, qkv_ptr,
                                                    MROWS, QKVD, DM);
    // 2) RoPE on Q and K in place
    rope_k<<<MROWS, 256>>>(cosb, sinb);

    // 3) Causal GQA flash attention
    attn_k<<<dim3(SS / AT_BM, NH, BB), 256, ATTN_SMEM_BYTES>>>();

    // 4) Output projection
    sgemm_k<<<dim3(DM / GBN, MROWS / GBM), 256>>>(attn_ptr, Wout, out,
                                                  MROWS, DM, DM);
}

// round 3
// speedup vs baseline: 1.8782x; 1.8782x over previous
#include <cuda_runtime.h>
#include <cuda_bf16.h>
#include <cstdint>
#include <math.h>

// Problem constants
#define BB      2
#define SS      2048
#define DM      4096
#define NH      32
#define NKV     8
#define HD      128
#define QKVD    6144          // (32 + 2*8) * 128
#define MROWS   4096          // B*S

// Scratch (allocation-free rule: __device__ globals)
__device__ float g_qkv [(size_t)MROWS * QKVD];   // qkv projection output (RoPE applied in place)
__device__ float g_attn[(size_t)MROWS * DM];     // attention output, [b*s, h*d]

// ---------------------------------------------------------------------------
// TF32 tensor-core GEMM: C[M,N] = A[M,K] @ B[K,N], row-major fp32 in/out.
// 128x128x32 CTA tile, 256 threads (8 warps as 2x4), 64x32 warp tile,
// mma.m16n8k8.tf32, cp.async 3-stage pipeline, cvt.rna rounding.
// ---------------------------------------------------------------------------
#define TBM 128
#define TBN 128
#define TBK 32
#define APITCH 36                 // As[m][k] pitch (floats) — conflict-free for A frags
#define BPITCH 136                // Bs[k][n] pitch (floats) — conflict-free for B frags
#define NSTAGE 3
#define AS_SZ (TBM * APITCH)      // 4608 floats
#define BS_SZ (TBK * BPITCH)      // 4352 floats
#define STAGE_SZ (AS_SZ + BS_SZ)  // 8960 floats
#define TF_SMEM_BYTES (NSTAGE * STAGE_SZ * 4)   // 107520 B

__device__ __forceinline__ void cp_async16(void* smem, const void* gmem) {
    uint32_t s = (uint32_t)__cvta_generic_to_shared(smem);
    asm volatile("cp.async.cg.shared.global [%0], [%1], 16;\n" :: "r"(s), "l"(gmem));
}
__device__ __forceinline__ uint32_t f2tf32(float x) {
    uint32_t r;
    asm("cvt.rna.tf32.f32 %0, %1;\n" : "=r"(r) : "f"(x));
    return r;
}
__device__ __forceinline__ void mma1688(float* d, const uint32_t* a, const uint32_t* b) {
    asm volatile(
        "mma.sync.aligned.m16n8k8.row.col.f32.tf32.tf32.f32 "
        "{%0,%1,%2,%3}, {%4,%5,%6,%7}, {%8,%9}, {%0,%1,%2,%3};\n"
        : "+f"(d[0]), "+f"(d[1]), "+f"(d[2]), "+f"(d[3])
        : "r"(a[0]), "r"(a[1]), "r"(a[2]), "r"(a[3]), "r"(b[0]), "r"(b[1]));
}

__global__ __launch_bounds__(256, 1) void tf32gemm_k(
    const float* __restrict__ A, const float* __restrict__ B,
    float* __restrict__ C, int M, int N, int K)
{
    extern __shared__ __align__(16) float ts[];

    const int tid  = threadIdx.x;
    const int lane = tid & 31;
    const int wid  = tid >> 5;
    const int wm   = wid >> 2;          // 0..1 -> 64 rows
    const int wn   = wid & 3;           // 0..3 -> 32 cols
    const int bm   = blockIdx.y * TBM;
    const int bn   = blockIdx.x * TBN;
    const int lq   = lane >> 2;         // lane/4: 0..7
    const int lr   = lane & 3;          // lane%4: 0..3

    // cp.async chunk coords (4 x 16B chunks each for A and B per k-tile)
    const int a_r[4]  = { tid >> 3, (tid + 256) >> 3, (tid + 512) >> 3, (tid + 768) >> 3 };
    const int a_c4    = (tid & 7) << 2;
    const int b_k[4]  = { tid >> 5, (tid + 256) >> 5, (tid + 512) >> 5, (tid + 768) >> 5 };
    const int b_n4    = (tid & 31) << 2;

    float acc[4][4][4];
    #pragma unroll
    for (int i = 0; i < 4; i++)
        #pragma unroll
        for (int j = 0; j < 4; j++)
            #pragma unroll
            for (int c = 0; c < 4; c++) acc[i][j][c] = 0.f;

    const int KT = K / TBK;

    auto issue = [&](int kt, int buf) {
        float* sA = ts + buf * STAGE_SZ;
        float* sB = sA + AS_SZ;
        const float* Ag = A + (size_t)bm * K + kt * TBK;
        const float* Bg = B + (size_t)(kt * TBK) * N + bn;
        #pragma unroll
        for (int i = 0; i < 4; i++)
            cp_async16(sA + a_r[i] * APITCH + a_c4, Ag + (size_t)a_r[i] * K + a_c4);
        #pragma unroll
        for (int i = 0; i < 4; i++)
            cp_async16(sB + b_k[i] * BPITCH + b_n4, Bg + (size_t)b_k[i] * N + b_n4);
        asm volatile("cp.async.commit_group;\n");
    };

    // prologue: stages 0 .. NSTAGE-2
    #pragma unroll
    for (int s = 0; s < NSTAGE - 1; s++) issue(s, s);

    for (int kt = 0; kt < KT; kt++) {
        asm volatile("cp.async.wait_group %0;\n" :: "n"(NSTAGE - 2));
        __syncthreads();

        const int nk = kt + NSTAGE - 1;
        if (nk < KT) issue(nk, nk % NSTAGE);
        else         asm volatile("cp.async.commit_group;\n");

        const float* sA = ts + (kt % NSTAGE) * STAGE_SZ;
        const float* sB = sA + AS_SZ;

        #pragma unroll
        for (int ks = 0; ks < 4; ks++) {
            const int k0 = ks * 8;
            uint32_t af[4][4], bf[4][2];
            #pragma unroll
            for (int mt = 0; mt < 4; mt++) {
                const float* p = sA + (wm * 64 + mt * 16 + lq) * APITCH + k0 + lr;
                af[mt][0] = f2tf32(p[0]);
                af[mt][1] = f2tf32(p[8 * APITCH]);
                af[mt][2] = f2tf32(p[4]);
                af[mt][3] = f2tf32(p[8 * APITCH + 4]);
            }
            #pragma unroll
            for (int nt = 0; nt < 4; nt++) {
                const float* p = sB + (k0 + lr) * BPITCH + wn * 32 + nt * 8 + lq;
                bf[nt][0] = f2tf32(p[0]);
                bf[nt][1] = f2tf32(p[4 * BPITCH]);
            }
            #pragma unroll
            for (int mt = 0; mt < 4; mt++)
                #pragma unroll
                for (int nt = 0; nt < 4; nt++)
                    mma1688(acc[mt][nt], af[mt], bf[nt]);
        }
    }

    // Epilogue
    #pragma unroll
    for (int mt = 0; mt < 4; mt++) {
        #pragma unroll
        for (int nt = 0; nt < 4; nt++) {
            const int row = bm + wm * 64 + mt * 16 + lq;
            const int col = bn + wn * 32 + nt * 8 + 2 * lr;
            float* c0 = C + (size_t)row * N + col;
            float* c1 = C + (size_t)(row + 8) * N + col;
            *(float2*)c0 = make_float2(acc[mt][nt][0], acc[mt][nt][1]);
            *(float2*)c1 = make_float2(acc[mt][nt][2], acc[mt][nt][3]);
        }
    }
}

// ---------------------------------------------------------------------------
// RoPE in place on Q (cols 0..4095) and K (cols 4096..5119) of g_qkv.
// ---------------------------------------------------------------------------
__global__ void rope_k(const float* __restrict__ cost, const float* __restrict__ sint)
{
    const int row = blockIdx.x;            // 0..4095
    const int s   = row & (SS - 1);
    float* q = g_qkv + (size_t)row * QKVD;

    for (int p = threadIdx.x; p < (NH + NKV) * 64; p += blockDim.x) {
        const int h = p >> 6;
        const int d = p & 63;
        const int base = (h < NH) ? h * HD : NH * HD + (h - NH) * HD;
        const float c  = cost[s * HD + d];
        const float sn = sint[s * HD + d];
        const float x1 = q[base + d];
        const float x2 = q[base + d + 64];
        q[base + d]      = x1 * c - x2 * sn;
        q[base + d + 64] = x2 * c + x1 * sn;
    }
}

// ---------------------------------------------------------------------------
// Flash attention, causal, fp32.  One CTA per (q-tile of 64, head, batch).
// ---------------------------------------------------------------------------
#define AT_BM   64
#define AT_BN   64
#define QT_P    68
#define SM_QT   0
#define SM_KT   (HD * QT_P)
#define SM_VS   (SM_KT + HD * QT_P)
#define SM_ST   (SM_VS + AT_BN * HD)
#define ATTN_SMEM_FLOATS (SM_ST + AT_BN * QT_P)
#define ATTN_SMEM_BYTES  (ATTN_SMEM_FLOATS * 4)

__global__ __launch_bounds__(256, 1) void attn_k()
{
    extern __shared__ __align__(16) float sm[];
    float* Qt = sm + SM_QT;
    float* Kt = sm + SM_KT;
    float* Vs = sm + SM_VS;
    float* St = sm + SM_ST;

    const int qt  = blockIdx.x;
    const int qh  = blockIdx.y;
    const int b   = blockIdx.z;
    const int kh  = qh >> 2;
    const int tid = threadIdx.x;
    const int rg  = tid >> 4;
    const int cg  = tid & 15;

    const float* Qg = g_qkv + (size_t)(b * SS + qt * AT_BM) * QKVD + qh * HD;
    const float* Kg = g_qkv + (size_t)(b * SS) * QKVD + NH * HD + kh * HD;
    const float* Vg = g_qkv + (size_t)(b * SS) * QKVD + (NH + NKV) * HD + kh * HD;

    const float scale = 0.08838834764831845f;

    for (int idx = tid; idx < AT_BM * HD; idx += 256) {
        const int r = idx >> 7, d = idx & 127;
        Qt[d * QT_P + r] = Qg[(size_t)r * QKVD + d] * scale;
    }

    float o[4][8];
    #pragma unroll
    for (int i = 0; i < 4; i++)
        #pragma unroll
        for (int j = 0; j < 8; j++) o[i][j] = 0.f;
    float m_r[4] = {-1e30f, -1e30f, -1e30f, -1e30f};
    float l_r[4] = {0.f, 0.f, 0.f, 0.f};

    for (int kt2 = 0; kt2 <= qt; kt2++) {
        __syncthreads();

        for (int idx = tid; idx < AT_BN * HD; idx += 256) {
            const int p = idx >> 7, d = idx & 127;
            const size_t grow = (size_t)(kt2 * AT_BN + p) * QKVD;
            Kt[d * QT_P + p] = Kg[grow + d];
            Vs[p * HD + d]   = Vg[grow + d];
        }
        __syncthreads();

        float sv[4][4];
        #pragma unroll
        for (int i = 0; i < 4; i++)
            #pragma unroll
            for (int j = 0; j < 4; j++) sv[i][j] = 0.f;

        #pragma unroll 4
        for (int d = 0; d < HD; d++) {
            const float4 qv = *(const float4*)&Qt[d * QT_P + 4 * rg];
            const float4 kv = *(const float4*)&Kt[d * QT_P + 4 * cg];
            const float qa[4] = {qv.x, qv.y, qv.z, qv.w};
            const float ka[4] = {kv.x, kv.y, kv.z, kv.w};
            #pragma unroll
            for (int i = 0; i < 4; i++)
                #pragma unroll
                for (int j = 0; j < 4; j++)
                    sv[i][j] = fmaf(qa[i], ka[j], sv[i][j]);
        }

        if (kt2 == qt) {
            #pragma unroll
            for (int i = 0; i < 4; i++)
                #pragma unroll
                for (int j = 0; j < 4; j++)
                    if (4 * cg + j > 4 * rg + i) sv[i][j] = -1e30f;
        }

        float scl[4];
        #pragma unroll
        for (int i = 0; i < 4; i++) {
            float mx = fmaxf(fmaxf(sv[i][0], sv[i][1]), fmaxf(sv[i][2], sv[i][3]));
            #pragma unroll
            for (int off = 1; off < 16; off <<= 1)
                mx = fmaxf(mx, __shfl_xor_sync(0xffffffffu, mx, off));
            const float mnew = fmaxf(m_r[i], mx);
            scl[i] = __expf(m_r[i] - mnew);
            m_r[i] = mnew;
            float rs = 0.f;
            #pragma unroll
            for (int j = 0; j < 4; j++) {
                const float p = __expf(sv[i][j] - mnew);
                sv[i][j] = p;
                rs += p;
            }
            #pragma unroll
            for (int off = 1; off < 16; off <<= 1)
                rs += __shfl_xor_sync(0xffffffffu, rs, off);
            l_r[i] = l_r[i] * scl[i] + rs;
        }

        #pragma unroll
        for (int i = 0; i < 4; i++)
            #pragma unroll
            for (int j = 0; j < 8; j++) o[i][j] *= scl[i];

        #pragma unroll
        for (int j = 0; j < 4; j++) {
            *(float4*)&St[(4 * cg + j) * QT_P + 4 * rg] =
                make_float4(sv[0][j], sv[1][j], sv[2][j], sv[3][j]);
        }
        __syncthreads();

        #pragma unroll 2
        for (int p = 0; p < AT_BN; p++) {
            const float4 pr = *(const float4*)&St[p * QT_P + 4 * rg];
            const float4 v0 = *(const float4*)&Vs[p * HD + 8 * cg];
            const float4 v1 = *(const float4*)&Vs[p * HD + 8 * cg + 4];
            const float pa[4] = {pr.x, pr.y, pr.z, pr.w};
            const float va[8] = {v0.x, v0.y, v0.z, v0.w, v1.x, v1.y, v1.z, v1.w};
            #pragma unroll
            for (int i = 0; i < 4; i++)
                #pragma unroll
                for (int j = 0; j < 8; j++)
                    o[i][j] = fmaf(pa[i], va[j], o[i][j]);
        }
    }

    float* Og = g_attn + (size_t)(b * SS + qt * AT_BM) * DM + qh * HD;
    #pragma unroll
    for (int i = 0; i < 4; i++) {
        const float inv = 1.f / l_r[i];
        float* dst = Og + (size_t)(4 * rg + i) * DM + 8 * cg;
        *(float4*)(dst)     = make_float4(o[i][0] * inv, o[i][1] * inv,
                                          o[i][2] * inv, o[i][3] * inv);
        *(float4*)(dst + 4) = make_float4(o[i][4] * inv, o[i][5] * inv,
                                          o[i][6] * inv, o[i][7] * inv);
    }
}

// ---------------------------------------------------------------------------
// Launch
// ---------------------------------------------------------------------------
extern "C" void kernel_launch(void* const* d_in, const int* in_sizes, int n_in,
                              void* d_out, int out_size)
{
    const float* hs   = (const float*)d_in[0];   // (B,S,4096) fp32
    const float* cosb = (const float*)d_in[1];   // (S,128)
    const float* sinb = (const float*)d_in[2];   // (S,128)
    const float* Wqkv = (const float*)d_in[3];   // (4096,6144)
    const float* Wout = (const float*)d_in[4];   // (4096,4096)
    float* out = (float*)d_out;                  // (B,S,4096)

    float* qkv_ptr;
    float* attn_ptr;
    cudaGetSymbolAddress((void**)&qkv_ptr,  g_qkv);
    cudaGetSymbolAddress((void**)&attn_ptr, g_attn);

    cudaFuncSetAttribute(tf32gemm_k, cudaFuncAttributeMaxDynamicSharedMemorySize,
                         TF_SMEM_BYTES);
    cudaFuncSetAttribute(attn_k, cudaFuncAttributeMaxDynamicSharedMemorySize,
                         ATTN_SMEM_BYTES);

    // 1) QKV projection (tf32 tensor cores)
    tf32gemm_k<<<dim3(QKVD / TBN, MROWS / TBM), 256, TF_SMEM_BYTES>>>(
        hs, Wqkv, qkv_ptr, MROWS, QKVD, DM);

    // 2) RoPE on Q and K in place
    rope_k<<<MROWS, 256>>>(cosb, sinb);

    // 3) Causal GQA flash attention (fp32)
    attn_k<<<dim3(SS / AT_BM, NH, BB), 256, ATTN_SMEM_BYTES>>>();

    // 4) Output projection (tf32 tensor cores)
    tf32gemm_k<<<dim3(DM / TBN, MROWS / TBM), 256, TF_SMEM_BYTES>>>(
        attn_ptr, Wout, out, MROWS, DM, DM);
}

// round 4
// speedup vs baseline: 2.2274x; 1.1859x over previous
#include <cuda_runtime.h>
#include <cuda_bf16.h>
#include <cstdint>
#include <math.h>

// Problem constants
#define BB      2
#define SS      2048
#define DM      4096
#define NH      32
#define NKV     8
#define HD      128
#define QKVD    6144          // (32 + 2*8) * 128
#define MROWS   4096          // B*S

// Scratch (allocation-free rule: __device__ globals)
__device__ float g_qkv [(size_t)MROWS * QKVD];   // qkv output (RoPE+rounding in place)
__device__ float g_attn[(size_t)MROWS * DM];     // attention output (tf32-rounded)
__device__ float g_rA  [(size_t)MROWS * DM];     // tf32-rounded hidden_states
__device__ float g_rWq [(size_t)DM * QKVD];      // tf32-rounded W_qkv
__device__ float g_rWo [(size_t)DM * DM];        // tf32-rounded W_out

__device__ __forceinline__ float f2tf32f(float x) {
    float r;
    asm("cvt.rna.tf32.f32 %0, %1;\n" : "=f"(r) : "f"(x));
    return r;
}
__device__ __forceinline__ void cp_async16(void* smem, const void* gmem) {
    uint32_t s = (uint32_t)__cvta_generic_to_shared(smem);
    asm volatile("cp.async.cg.shared.global [%0], [%1], 16;\n" :: "r"(s), "l"(gmem));
}
__device__ __forceinline__ void mma1688(float* d, const uint32_t* a, const uint32_t* b) {
    asm volatile(
        "mma.sync.aligned.m16n8k8.row.col.f32.tf32.tf32.f32 "
        "{%0,%1,%2,%3}, {%4,%5,%6,%7}, {%8,%9}, {%0,%1,%2,%3};\n"
        : "+f"(d[0]), "+f"(d[1]), "+f"(d[2]), "+f"(d[3])
        : "r"(a[0]), "r"(a[1]), "r"(a[2]), "r"(a[3]), "r"(b[0]), "r"(b[1]));
}

// ---------------------------------------------------------------------------
// Elementwise tf32 rounding pass (float4 grid-stride)
// ---------------------------------------------------------------------------
__global__ void round_k(const float* __restrict__ in, float* __restrict__ out, size_t n4)
{
    for (size_t i = (size_t)blockIdx.x * blockDim.x + threadIdx.x; i < n4;
         i += (size_t)gridDim.x * blockDim.x) {
        float4 v = ((const float4*)in)[i];
        v.x = f2tf32f(v.x); v.y = f2tf32f(v.y);
        v.z = f2tf32f(v.z); v.w = f2tf32f(v.w);
        ((float4*)out)[i] = v;
    }
}

// ---------------------------------------------------------------------------
// TF32 tensor-core GEMM: C[M,N] = A[M,K] @ B[K,N]. Inputs PRE-ROUNDED to tf32
// (no cvt in the hot loop). 128x128x32 tile, 256 thr, cp.async 3-stage.
// ---------------------------------------------------------------------------
#define TBM 128
#define TBN 128
#define TBK 32
#define APITCH 36
#define BPITCH 136
#define NSTAGE 3
#define AS_SZ (TBM * APITCH)
#define BS_SZ (TBK * BPITCH)
#define STAGE_SZ (AS_SZ + BS_SZ)
#define TF_SMEM_BYTES (NSTAGE * STAGE_SZ * 4)

__global__ __launch_bounds__(256, 1) void tf32gemm_k(
    const float* __restrict__ A, const float* __restrict__ B,
    float* __restrict__ C, int M, int N, int K)
{
    extern __shared__ __align__(16) float ts[];

    const int tid  = threadIdx.x;
    const int lane = tid & 31;
    const int wid  = tid >> 5;
    const int wm   = wid >> 2;
    const int wn   = wid & 3;
    const int bm   = blockIdx.y * TBM;
    const int bn   = blockIdx.x * TBN;
    const int lq   = lane >> 2;
    const int lr   = lane & 3;

    const int a_r[4]  = { tid >> 3, (tid + 256) >> 3, (tid + 512) >> 3, (tid + 768) >> 3 };
    const int a_c4    = (tid & 7) << 2;
    const int b_k[4]  = { tid >> 5, (tid + 256) >> 5, (tid + 512) >> 5, (tid + 768) >> 5 };
    const int b_n4    = (tid & 31) << 2;

    float acc[4][4][4];
    #pragma unroll
    for (int i = 0; i < 4; i++)
        #pragma unroll
        for (int j = 0; j < 4; j++)
            #pragma unroll
            for (int c = 0; c < 4; c++) acc[i][j][c] = 0.f;

    const int KT = K / TBK;

    auto issue = [&](int kt, int buf) {
        float* sA = ts + buf * STAGE_SZ;
        float* sB = sA + AS_SZ;
        const float* Ag = A + (size_t)bm * K + kt * TBK;
        const float* Bg = B + (size_t)(kt * TBK) * N + bn;
        #pragma unroll
        for (int i = 0; i < 4; i++)
            cp_async16(sA + a_r[i] * APITCH + a_c4, Ag + (size_t)a_r[i] * K + a_c4);
        #pragma unroll
        for (int i = 0; i < 4; i++)
            cp_async16(sB + b_k[i] * BPITCH + b_n4, Bg + (size_t)b_k[i] * N + b_n4);
        asm volatile("cp.async.commit_group;\n");
    };

    #pragma unroll
    for (int s = 0; s < NSTAGE - 1; s++) issue(s, s);

    for (int kt = 0; kt < KT; kt++) {
        asm volatile("cp.async.wait_group %0;\n" :: "n"(NSTAGE - 2));
        __syncthreads();

        const int nk = kt + NSTAGE - 1;
        if (nk < KT) issue(nk, nk % NSTAGE);
        else         asm volatile("cp.async.commit_group;\n");

        const float* sA = ts + (kt % NSTAGE) * STAGE_SZ;
        const float* sB = sA + AS_SZ;

        #pragma unroll
        for (int ks = 0; ks < 4; ks++) {
            const int k0 = ks * 8;
            uint32_t af[4][4], bf[4][2];
            #pragma unroll
            for (int mt = 0; mt < 4; mt++) {
                const float* p = sA + (wm * 64 + mt * 16 + lq) * APITCH + k0 + lr;
                af[mt][0] = __float_as_uint(p[0]);
                af[mt][1] = __float_as_uint(p[8 * APITCH]);
                af[mt][2] = __float_as_uint(p[4]);
                af[mt][3] = __float_as_uint(p[8 * APITCH + 4]);
            }
            #pragma unroll
            for (int nt = 0; nt < 4; nt++) {
                const float* p = sB + (k0 + lr) * BPITCH + wn * 32 + nt * 8 + lq;
                bf[nt][0] = __float_as_uint(p[0]);
                bf[nt][1] = __float_as_uint(p[4 * BPITCH]);
            }
            #pragma unroll
            for (int mt = 0; mt < 4; mt++)
                #pragma unroll
                for (int nt = 0; nt < 4; nt++)
                    mma1688(acc[mt][nt], af[mt], bf[nt]);
        }
    }

    #pragma unroll
    for (int mt = 0; mt < 4; mt++) {
        #pragma unroll
        for (int nt = 0; nt < 4; nt++) {
            const int row = bm + wm * 64 + mt * 16 + lq;
            const int col = bn + wn * 32 + nt * 8 + 2 * lr;
            float* c0 = C + (size_t)row * N + col;
            float* c1 = C + (size_t)(row + 8) * N + col;
            *(float2*)c0 = make_float2(acc[mt][nt][0], acc[mt][nt][1]);
            *(float2*)c1 = make_float2(acc[mt][nt][2], acc[mt][nt][3]);
        }
    }
}

// ---------------------------------------------------------------------------
// RoPE in place on Q/K of g_qkv + tf32 rounding of Q, K, AND V.
// ---------------------------------------------------------------------------
__global__ void rope_k(const float* __restrict__ cost, const float* __restrict__ sint)
{
    const int row = blockIdx.x;            // 0..4095
    const int s   = row & (SS - 1);
    float* q = g_qkv + (size_t)row * QKVD;

    const int NROPE = (NH + NKV) * 64;     // 2560 rotation pairs
    const int NV    = NKV * HD;            // 1024 V elements
    for (int p = threadIdx.x; p < NROPE + NV; p += blockDim.x) {
        if (p < NROPE) {
            const int h = p >> 6;
            const int d = p & 63;
            const int base = h * HD;       // q heads then k heads are contiguous
            const float c  = cost[s * HD + d];
            const float sn = sint[s * HD + d];
            const float x1 = q[base + d];
            const float x2 = q[base + d + 64];
            q[base + d]      = f2tf32f(x1 * c - x2 * sn);
            q[base + d + 64] = f2tf32f(x2 * c + x1 * sn);
        } else {
            const int idx = (NH + NKV) * HD + (p - NROPE);
            q[idx] = f2tf32f(q[idx]);
        }
    }
}

// ---------------------------------------------------------------------------
// Flash attention with tf32 tensor cores. BM=128 q rows, BN=64 keys,
// 8 warps (each owns 16 q rows). All fragment loads bank-conflict-free.
// ---------------------------------------------------------------------------
#define FBM 128
#define FBN 64
#define QP  132     // ≡4 mod 32
#define KP  132
#define VP  136     // ≡8 mod 32
#define SP  68      // ≡4 mod 32
#define FA_SMEM_FLOATS (FBM*QP + FBN*KP + FBN*VP + FBM*SP)
#define FA_SMEM_BYTES  (FA_SMEM_FLOATS * 4)   // 171008 B

__global__ __launch_bounds__(256, 1) void fattn_k()
{
    extern __shared__ __align__(16) float sm[];
    float* Qs = sm;                       // [128][QP]
    float* Ks = Qs + FBM * QP;            // [64][KP]
    float* Vs = Ks + FBN * KP;            // [64][VP]
    float* Ps = Vs + FBN * VP;            // [128][SP]

    const int qt  = blockIdx.x;           // 0..15
    const int qh  = blockIdx.y;
    const int b   = blockIdx.z;
    const int kh  = qh >> 2;
    const int tid = threadIdx.x;
    const int lane = tid & 31;
    const int w   = tid >> 5;
    const int lq  = lane >> 2;
    const int lr  = lane & 3;
    const int m0  = w * 16;               // warp's q-row offset in tile

    const float* Qg = g_qkv + (size_t)(b * SS + qt * FBM) * QKVD + qh * HD;
    const float* Kg = g_qkv + (size_t)(b * SS) * QKVD + NH * HD + kh * HD;
    const float* Vg = g_qkv + (size_t)(b * SS) * QKVD + (NH + NKV) * HD + kh * HD;

    const float scale = 0.08838834764831845f;   // applied post-MMA

    // Load Q (raw, already tf32-rounded)
    for (int i = tid; i < FBM * (HD / 4); i += 256) {
        const int r = i >> 5, c4 = (i & 31) << 2;
        *(float4*)&Qs[r * QP + c4] = *(const float4*)(Qg + (size_t)r * QKVD + c4);
    }

    float oacc[16][4];
    #pragma unroll
    for (int i = 0; i < 16; i++)
        #pragma unroll
        for (int c = 0; c < 4; c++) oacc[i][c] = 0.f;
    float mrow0 = -1e30f, mrow1 = -1e30f;
    float lrow0 = 0.f,    lrow1 = 0.f;

    const int ktmax = 2 * qt + 2;
    for (int kt2 = 0; kt2 < ktmax; kt2++) {
        // Fill K, V tiles
        for (int i = tid; i < FBN * (HD / 4); i += 256) {
            const int r = i >> 5, c4 = (i & 31) << 2;
            const size_t grow = (size_t)(kt2 * FBN + r) * QKVD;
            *(float4*)&Ks[r * KP + c4] = *(const float4*)(Kg + grow + c4);
            *(float4*)&Vs[r * VP + c4] = *(const float4*)(Vg + grow + c4);
        }
        __syncthreads();

        // S = Q K^T  (warp: 16 rows x 64 keys, 8 n-tiles)
        float sacc[8][4];
        #pragma unroll
        for (int i = 0; i < 8; i++)
            #pragma unroll
            for (int c = 0; c < 4; c++) sacc[i][c] = 0.f;

        #pragma unroll
        for (int k = 0; k < 16; k++) {
            const int k0 = k * 8;
            uint32_t a[4];
            const float* qp = Qs + (m0 + lq) * QP + k0 + lr;
            a[0] = __float_as_uint(qp[0]);
            a[1] = __float_as_uint(qp[8 * QP]);
            a[2] = __float_as_uint(qp[4]);
            a[3] = __float_as_uint(qp[8 * QP + 4]);
            #pragma unroll
            for (int nt = 0; nt < 8; nt++) {
                uint32_t bfr[2];
                const float* kp = Ks + (nt * 8 + lq) * KP + k0 + lr;
                bfr[0] = __float_as_uint(kp[0]);
                bfr[1] = __float_as_uint(kp[4]);
                mma1688(sacc[nt], a, bfr);
            }
        }

        // Scale + causal mask
        const bool need_mask = (kt2 >= 2 * qt);
        const int r0 = qt * FBM + m0 + lq;
        const int r1 = r0 + 8;
        #pragma unroll
        for (int nt = 0; nt < 8; nt++) {
            const int colb = kt2 * FBN + nt * 8 + 2 * lr;
            #pragma unroll
            for (int c = 0; c < 4; c++) sacc[nt][c] *= scale;
            if (need_mask) {
                if (colb     > r0) sacc[nt][0] = -1e30f;
                if (colb + 1 > r0) sacc[nt][1] = -1e30f;
                if (colb     > r1) sacc[nt][2] = -1e30f;
                if (colb + 1 > r1) sacc[nt][3] = -1e30f;
            }
        }

        // Online softmax (rows lq and lq+8; reduce across the 4 lr lanes)
        float mx0 = -1e30f, mx1 = -1e30f;
        #pragma unroll
        for (int nt = 0; nt < 8; nt++) {
            mx0 = fmaxf(mx0, fmaxf(sacc[nt][0], sacc[nt][1]));
            mx1 = fmaxf(mx1, fmaxf(sacc[nt][2], sacc[nt][3]));
        }
        mx0 = fmaxf(mx0, __shfl_xor_sync(0xffffffffu, mx0, 1));
        mx0 = fmaxf(mx0, __shfl_xor_sync(0xffffffffu, mx0, 2));
        mx1 = fmaxf(mx1, __shfl_xor_sync(0xffffffffu, mx1, 1));
        mx1 = fmaxf(mx1, __shfl_xor_sync(0xffffffffu, mx1, 2));

        const float mn0 = fmaxf(mrow0, mx0);
        const float mn1 = fmaxf(mrow1, mx1);
        const float scl0 = __expf(mrow0 - mn0);
        const float scl1 = __expf(mrow1 - mn1);
        mrow0 = mn0; mrow1 = mn1;

        float rs0 = 0.f, rs1 = 0.f;
        #pragma unroll
        for (int nt = 0; nt < 8; nt++) {
            float p0 = f2tf32f(__expf(sacc[nt][0] - mn0));
            float p1 = f2tf32f(__expf(sacc[nt][1] - mn0));
            float p2 = f2tf32f(__expf(sacc[nt][2] - mn1));
            float p3 = f2tf32f(__expf(sacc[nt][3] - mn1));
            rs0 += p0 + p1;
            rs1 += p2 + p3;
            const int cb = nt * 8 + 2 * lr;
            *(float2*)&Ps[(m0 + lq) * SP + cb]     = make_float2(p0, p1);
            *(float2*)&Ps[(m0 + lq + 8) * SP + cb] = make_float2(p2, p3);
        }
        rs0 += __shfl_xor_sync(0xffffffffu, rs0, 1);
        rs0 += __shfl_xor_sync(0xffffffffu, rs0, 2);
        rs1 += __shfl_xor_sync(0xffffffffu, rs1, 1);
        rs1 += __shfl_xor_sync(0xffffffffu, rs1, 2);
        lrow0 = lrow0 * scl0 + rs0;
        lrow1 = lrow1 * scl1 + rs1;

        // Rescale O
        #pragma unroll
        for (int nt = 0; nt < 16; nt++) {
            oacc[nt][0] *= scl0; oacc[nt][1] *= scl0;
            oacc[nt][2] *= scl1; oacc[nt][3] *= scl1;
        }
        __syncwarp();   // P written by this warp's lanes, read cross-lane below

        // O += P V  (k over 8 key-chunks, nt over 16 d-tiles)
        #pragma unroll
        for (int k = 0; k < 8; k++) {
            const int k0 = k * 8;
            uint32_t a[4];
            const float* pp = Ps + (m0 + lq) * SP + k0 + lr;
            a[0] = __float_as_uint(pp[0]);
            a[1] = __float_as_uint(pp[8 * SP]);
            a[2] = __float_as_uint(pp[4]);
            a[3] = __float_as_uint(pp[8 * SP + 4]);
            #pragma unroll
            for (int nt = 0; nt < 16; nt++) {
                uint32_t bfr[2];
                const float* vp = Vs + (k0 + lr) * VP + nt * 8 + lq;
                bfr[0] = __float_as_uint(vp[0]);
                bfr[1] = __float_as_uint(vp[4 * VP]);
                mma1688(oacc[nt], a, bfr);
            }
        }
        __syncthreads();   // before next tile overwrites K/V
    }

    // Normalize + round (feeds GEMM2 as tf32 A operand) + store
    const float inv0 = 1.f / lrow0;
    const float inv1 = 1.f / lrow1;
    float* Og = g_attn + (size_t)(b * SS + qt * FBM + m0 + lq) * DM + qh * HD;
    #pragma unroll
    for (int nt = 0; nt < 16; nt++) {
        const int cb = nt * 8 + 2 * lr;
        *(float2*)(Og + cb) =
            make_float2(f2tf32f(oacc[nt][0] * inv0), f2tf32f(oacc[nt][1] * inv0));
        *(float2*)(Og + (size_t)8 * DM + cb) =
            make_float2(f2tf32f(oacc[nt][2] * inv1), f2tf32f(oacc[nt][3] * inv1));
    }
}

// ---------------------------------------------------------------------------
// Launch
// ---------------------------------------------------------------------------
extern "C" void kernel_launch(void* const* d_in, const int* in_sizes, int n_in,
                              void* d_out, int out_size)
{
    const float* hs   = (const float*)d_in[0];
    const float* cosb = (const float*)d_in[1];
    const float* sinb = (const float*)d_in[2];
    const float* Wqkv = (const float*)d_in[3];
    const float* Wout = (const float*)d_in[4];
    float* out = (float*)d_out;

    float *qkv_ptr, *attn_ptr, *rA, *rWq, *rWo;
    cudaGetSymbolAddress((void**)&qkv_ptr,  g_qkv);
    cudaGetSymbolAddress((void**)&attn_ptr, g_attn);
    cudaGetSymbolAddress((void**)&rA,  g_rA);
    cudaGetSymbolAddress((void**)&rWq, g_rWq);
    cudaGetSymbolAddress((void**)&rWo, g_rWo);

    cudaFuncSetAttribute(tf32gemm_k, cudaFuncAttributeMaxDynamicSharedMemorySize,
                         TF_SMEM_BYTES);
    cudaFuncSetAttribute(fattn_k, cudaFuncAttributeMaxDynamicSharedMemorySize,
                         FA_SMEM_BYTES);

    // 0) tf32 pre-rounding of all GEMM inputs
    round_k<<<592, 256>>>(hs,   rA,  (size_t)MROWS * DM / 4);
    round_k<<<592, 256>>>(Wqkv, rWq, (size_t)DM * QKVD / 4);
    round_k<<<592, 256>>>(Wout, rWo, (size_t)DM * DM / 4);

    // 1) QKV projection
    tf32gemm_k<<<dim3(QKVD / TBN, MROWS / TBM), 256, TF_SMEM_BYTES>>>(
        rA, rWq, qkv_ptr, MROWS, QKVD, DM);

    // 2) RoPE + tf32 rounding of Q/K/V
    rope_k<<<MROWS, 256>>>(cosb, sinb);

    // 3) Causal GQA flash attention (tf32 tensor cores)
    fattn_k<<<dim3(SS / FBM, NH, BB), 256, FA_SMEM_BYTES>>>();

    // 4) Output projection
    tf32gemm_k<<<dim3(DM / TBN, MROWS / TBM), 256, TF_SMEM_BYTES>>>(
        attn_ptr, rWo, out, MROWS, DM, DM);
}

// round 5
// speedup vs baseline: 3.7782x; 1.6962x over previous
#include <cuda_runtime.h>
#include <cuda_bf16.h>
#include <cstdint>
#include <math.h>

// Problem constants
#define BB      2
#define SS      2048
#define DM      4096
#define NH      32
#define NKV     8
#define HD      128
#define QKVD    6144          // (32 + 2*8) * 128
#define MROWS   4096          // B*S

// Scratch (allocation-free rule: __device__ globals)
__device__ float g_qkv [(size_t)MROWS * QKVD];   // qkv output (RoPE+rounding in place)
__device__ float g_attn[(size_t)MROWS * DM];     // attention output (tf32-rounded)
__device__ float g_rA  [(size_t)MROWS * DM];     // tf32-rounded hidden_states
__device__ float g_rWq [(size_t)DM * QKVD];      // tf32-rounded W_qkv
__device__ float g_rWo [(size_t)DM * DM];        // tf32-rounded W_out

__device__ __forceinline__ float f2tf32f(float x) {
    float r;
    asm("cvt.rna.tf32.f32 %0, %1;\n" : "=f"(r) : "f"(x));
    return r;
}
__device__ __forceinline__ void cp_async16(void* smem, const void* gmem) {
    uint32_t s = (uint32_t)__cvta_generic_to_shared(smem);
    asm volatile("cp.async.cg.shared.global [%0], [%1], 16;\n" :: "r"(s), "l"(gmem));
}
__device__ __forceinline__ void mma1688(float* d, const uint32_t* a, const uint32_t* b) {
    asm volatile(
        "mma.sync.aligned.m16n8k8.row.col.f32.tf32.tf32.f32 "
        "{%0,%1,%2,%3}, {%4,%5,%6,%7}, {%8,%9}, {%0,%1,%2,%3};\n"
        : "+f"(d[0]), "+f"(d[1]), "+f"(d[2]), "+f"(d[3])
        : "r"(a[0]), "r"(a[1]), "r"(a[2]), "r"(a[3]), "r"(b[0]), "r"(b[1]));
}

// ---------------------------------------------------------------------------
// Elementwise tf32 rounding pass (float4 grid-stride)
// ---------------------------------------------------------------------------
__global__ void round_k(const float* __restrict__ in, float* __restrict__ out, size_t n4)
{
    for (size_t i = (size_t)blockIdx.x * blockDim.x + threadIdx.x; i < n4;
         i += (size_t)gridDim.x * blockDim.x) {
        float4 v = ((const float4*)in)[i];
        v.x = f2tf32f(v.x); v.y = f2tf32f(v.y);
        v.z = f2tf32f(v.z); v.w = f2tf32f(v.w);
        ((float4*)out)[i] = v;
    }
}

// ---------------------------------------------------------------------------
// TF32 tensor-core GEMM: C[M,N] = A[M,K] @ B[K,N]. Inputs PRE-ROUNDED to tf32.
// 128x128x32 tile, 256 thr, cp.async 2-stage, 2 CTAs/SM for latency hiding.
// ---------------------------------------------------------------------------
#define TBM 128
#define TBN 128
#define TBK 32
#define APITCH 36
#define BPITCH 136
#define NSTAGE 2
#define AS_SZ (TBM * APITCH)
#define BS_SZ (TBK * BPITCH)
#define STAGE_SZ (AS_SZ + BS_SZ)
#define TF_SMEM_BYTES (NSTAGE * STAGE_SZ * 4)   // 71680 B -> 2 CTAs/SM

__global__ __launch_bounds__(256, 2) void tf32gemm_k(
    const float* __restrict__ A, const float* __restrict__ B,
    float* __restrict__ C, int M, int N, int K)
{
    extern __shared__ __align__(16) float ts[];

    const int tid  = threadIdx.x;
    const int lane = tid & 31;
    const int wid  = tid >> 5;
    const int wm   = wid >> 2;
    const int wn   = wid & 3;
    const int bm   = blockIdx.y * TBM;
    const int bn   = blockIdx.x * TBN;
    const int lq   = lane >> 2;
    const int lr   = lane & 3;

    const int a_r[4]  = { tid >> 3, (tid + 256) >> 3, (tid + 512) >> 3, (tid + 768) >> 3 };
    const int a_c4    = (tid & 7) << 2;
    const int b_k[4]  = { tid >> 5, (tid + 256) >> 5, (tid + 512) >> 5, (tid + 768) >> 5 };
    const int b_n4    = (tid & 31) << 2;

    float acc[4][4][4];
    #pragma unroll
    for (int i = 0; i < 4; i++)
        #pragma unroll
        for (int j = 0; j < 4; j++)
            #pragma unroll
            for (int c = 0; c < 4; c++) acc[i][j][c] = 0.f;

    const int KT = K / TBK;

    auto issue = [&](int kt, int buf) {
        float* sA = ts + buf * STAGE_SZ;
        float* sB = sA + AS_SZ;
        const float* Ag = A + (size_t)bm * K + kt * TBK;
        const float* Bg = B + (size_t)(kt * TBK) * N + bn;
        #pragma unroll
        for (int i = 0; i < 4; i++)
            cp_async16(sA + a_r[i] * APITCH + a_c4, Ag + (size_t)a_r[i] * K + a_c4);
        #pragma unroll
        for (int i = 0; i < 4; i++)
            cp_async16(sB + b_k[i] * BPITCH + b_n4, Bg + (size_t)b_k[i] * N + b_n4);
        asm volatile("cp.async.commit_group;\n");
    };

    issue(0, 0);

    for (int kt = 0; kt < KT; kt++) {
        asm volatile("cp.async.wait_group 0;\n");
        __syncthreads();

        const int nk = kt + 1;
        if (nk < KT) issue(nk, nk & 1);

        const float* sA = ts + (kt & 1) * STAGE_SZ;
        const float* sB = sA + AS_SZ;

        #pragma unroll
        for (int ks = 0; ks < 4; ks++) {
            const int k0 = ks * 8;
            uint32_t af[4][4], bf[4][2];
            #pragma unroll
            for (int mt = 0; mt < 4; mt++) {
                const float* p = sA + (wm * 64 + mt * 16 + lq) * APITCH + k0 + lr;
                af[mt][0] = __float_as_uint(p[0]);
                af[mt][1] = __float_as_uint(p[8 * APITCH]);
                af[mt][2] = __float_as_uint(p[4]);
                af[mt][3] = __float_as_uint(p[8 * APITCH + 4]);
            }
            #pragma unroll
            for (int nt = 0; nt < 4; nt++) {
                const float* p = sB + (k0 + lr) * BPITCH + wn * 32 + nt * 8 + lq;
                bf[nt][0] = __float_as_uint(p[0]);
                bf[nt][1] = __float_as_uint(p[4 * BPITCH]);
            }
            #pragma unroll
            for (int mt = 0; mt < 4; mt++)
                #pragma unroll
                for (int nt = 0; nt < 4; nt++)
                    mma1688(acc[mt][nt], af[mt], bf[nt]);
        }
        __syncthreads();
    }

    #pragma unroll
    for (int mt = 0; mt < 4; mt++) {
        #pragma unroll
        for (int nt = 0; nt < 4; nt++) {
            const int row = bm + wm * 64 + mt * 16 + lq;
            const int col = bn + wn * 32 + nt * 8 + 2 * lr;
            float* c0 = C + (size_t)row * N + col;
            float* c1 = C + (size_t)(row + 8) * N + col;
            *(float2*)c0 = make_float2(acc[mt][nt][0], acc[mt][nt][1]);
            *(float2*)c1 = make_float2(acc[mt][nt][2], acc[mt][nt][3]);
        }
    }
}

// ---------------------------------------------------------------------------
// RoPE in place on Q/K of g_qkv + tf32 rounding of Q, K, AND V.
// ---------------------------------------------------------------------------
__global__ void rope_k(const float* __restrict__ cost, const float* __restrict__ sint)
{
    const int row = blockIdx.x;            // 0..4095
    const int s   = row & (SS - 1);
    float* q = g_qkv + (size_t)row * QKVD;

    const int NROPE = (NH + NKV) * 64;     // 2560 rotation pairs
    const int NV    = NKV * HD;            // 1024 V elements
    for (int p = threadIdx.x; p < NROPE + NV; p += blockDim.x) {
        if (p < NROPE) {
            const int h = p >> 6;
            const int d = p & 63;
            const int base = h * HD;
            const float c  = cost[s * HD + d];
            const float sn = sint[s * HD + d];
            const float x1 = q[base + d];
            const float x2 = q[base + d + 64];
            q[base + d]      = f2tf32f(x1 * c - x2 * sn);
            q[base + d + 64] = f2tf32f(x2 * c + x1 * sn);
        } else {
            const int idx = (NH + NKV) * HD + (p - NROPE);
            q[idx] = f2tf32f(q[idx]);
        }
    }
}

// ---------------------------------------------------------------------------
// Flash attention with tf32 tensor cores. BM=128 q rows, BN=64 keys,
// 8 warps (each owns 16 q rows). All fragment loads bank-conflict-free.
// ---------------------------------------------------------------------------
#define FBM 128
#define FBN 64
#define QP  132     // ≡4 mod 32
#define KP  132
#define VP  136     // ≡8 mod 32
#define SP  68      // ≡4 mod 32
#define FA_SMEM_FLOATS (FBM*QP + FBN*KP + FBN*VP + FBM*SP)
#define FA_SMEM_BYTES  (FA_SMEM_FLOATS * 4)   // 171008 B

__global__ __launch_bounds__(256, 1) void fattn_k()
{
    extern __shared__ __align__(16) float sm[];
    float* Qs = sm;                       // [128][QP]
    float* Ks = Qs + FBM * QP;            // [64][KP]
    float* Vs = Ks + FBN * KP;            // [64][VP]
    float* Ps = Vs + FBN * VP;            // [128][SP]

    const int qt  = blockIdx.x;           // 0..15
    const int qh  = blockIdx.y;
    const int b   = blockIdx.z;
    const int kh  = qh >> 2;
    const int tid = threadIdx.x;
    const int lane = tid & 31;
    const int w   = tid >> 5;
    const int lq  = lane >> 2;
    const int lr  = lane & 3;
    const int m0  = w * 16;

    const float* Qg = g_qkv + (size_t)(b * SS + qt * FBM) * QKVD + qh * HD;
    const float* Kg = g_qkv + (size_t)(b * SS) * QKVD + NH * HD + kh * HD;
    const float* Vg = g_qkv + (size_t)(b * SS) * QKVD + (NH + NKV) * HD + kh * HD;

    const float scale = 0.08838834764831845f;

    for (int i = tid; i < FBM * (HD / 4); i += 256) {
        const int r = i >> 5, c4 = (i & 31) << 2;
        *(float4*)&Qs[r * QP + c4] = *(const float4*)(Qg + (size_t)r * QKVD + c4);
    }

    float oacc[16][4];
    #pragma unroll
    for (int i = 0; i < 16; i++)
        #pragma unroll
        for (int c = 0; c < 4; c++) oacc[i][c] = 0.f;
    float mrow0 = -1e30f, mrow1 = -1e30f;
    float lrow0 = 0.f,    lrow1 = 0.f;

    const int ktmax = 2 * qt + 2;
    for (int kt2 = 0; kt2 < ktmax; kt2++) {
        for (int i = tid; i < FBN * (HD / 4); i += 256) {
            const int r = i >> 5, c4 = (i & 31) << 2;
            const size_t grow = (size_t)(kt2 * FBN + r) * QKVD;
            *(float4*)&Ks[r * KP + c4] = *(const float4*)(Kg + grow + c4);
            *(float4*)&Vs[r * VP + c4] = *(const float4*)(Vg + grow + c4);
        }
        __syncthreads();

        float sacc[8][4];
        #pragma unroll
        for (int i = 0; i < 8; i++)
            #pragma unroll
            for (int c = 0; c < 4; c++) sacc[i][c] = 0.f;

        #pragma unroll
        for (int k = 0; k < 16; k++) {
            const int k0 = k * 8;
            uint32_t a[4];
            const float* qp = Qs + (m0 + lq) * QP + k0 + lr;
            a[0] = __float_as_uint(qp[0]);
            a[1] = __float_as_uint(qp[8 * QP]);
            a[2] = __float_as_uint(qp[4]);
            a[3] = __float_as_uint(qp[8 * QP + 4]);
            #pragma unroll
            for (int nt = 0; nt < 8; nt++) {
                uint32_t bfr[2];
                const float* kp = Ks + (nt * 8 + lq) * KP + k0 + lr;
                bfr[0] = __float_as_uint(kp[0]);
                bfr[1] = __float_as_uint(kp[4]);
                mma1688(sacc[nt], a, bfr);
            }
        }

        const bool need_mask = (kt2 >= 2 * qt);
        const int r0 = qt * FBM + m0 + lq;
        const int r1 = r0 + 8;
        #pragma unroll
        for (int nt = 0; nt < 8; nt++) {
            const int colb = kt2 * FBN + nt * 8 + 2 * lr;
            #pragma unroll
            for (int c = 0; c < 4; c++) sacc[nt][c] *= scale;
            if (need_mask) {
                if (colb     > r0) sacc[nt][0] = -1e30f;
                if (colb + 1 > r0) sacc[nt][1] = -1e30f;
                if (colb     > r1) sacc[nt][2] = -1e30f;
                if (colb + 1 > r1) sacc[nt][3] = -1e30f;
            }
        }

        float mx0 = -1e30f, mx1 = -1e30f;
        #pragma unroll
        for (int nt = 0; nt < 8; nt++) {
            mx0 = fmaxf(mx0, fmaxf(sacc[nt][0], sacc[nt][1]));
            mx1 = fmaxf(mx1, fmaxf(sacc[nt][2], sacc[nt][3]));
        }
        mx0 = fmaxf(mx0, __shfl_xor_sync(0xffffffffu, mx0, 1));
        mx0 = fmaxf(mx0, __shfl_xor_sync(0xffffffffu, mx0, 2));
        mx1 = fmaxf(mx1, __shfl_xor_sync(0xffffffffu, mx1, 1));
        mx1 = fmaxf(mx1, __shfl_xor_sync(0xffffffffu, mx1, 2));

        const float mn0 = fmaxf(mrow0, mx0);
        const float mn1 = fmaxf(mrow1, mx1);
        const float scl0 = __expf(mrow0 - mn0);
        const float scl1 = __expf(mrow1 - mn1);
        mrow0 = mn0; mrow1 = mn1;

        float rs0 = 0.f, rs1 = 0.f;
        #pragma unroll
        for (int nt = 0; nt < 8; nt++) {
            float p0 = f2tf32f(__expf(sacc[nt][0] - mn0));
            float p1 = f2tf32f(__expf(sacc[nt][1] - mn0));
            float p2 = f2tf32f(__expf(sacc[nt][2] - mn1));
            float p3 = f2tf32f(__expf(sacc[nt][3] - mn1));
            rs0 += p0 + p1;
            rs1 += p2 + p3;
            const int cb = nt * 8 + 2 * lr;
            *(float2*)&Ps[(m0 + lq) * SP + cb]     = make_float2(p0, p1);
            *(float2*)&Ps[(m0 + lq + 8) * SP + cb] = make_float2(p2, p3);
        }
        rs0 += __shfl_xor_sync(0xffffffffu, rs0, 1);
        rs0 += __shfl_xor_sync(0xffffffffu, rs0, 2);
        rs1 += __shfl_xor_sync(0xffffffffu, rs1, 1);
        rs1 += __shfl_xor_sync(0xffffffffu, rs1, 2);
        lrow0 = lrow0 * scl0 + rs0;
        lrow1 = lrow1 * scl1 + rs1;

        #pragma unroll
        for (int nt = 0; nt < 16; nt++) {
            oacc[nt][0] *= scl0; oacc[nt][1] *= scl0;
            oacc[nt][2] *= scl1; oacc[nt][3] *= scl1;
        }
        __syncwarp();

        #pragma unroll
        for (int k = 0; k < 8; k++) {
            const int k0 = k * 8;
            uint32_t a[4];
            const float* pp = Ps + (m0 + lq) * SP + k0 + lr;
            a[0] = __float_as_uint(pp[0]);
            a[1] = __float_as_uint(pp[8 * SP]);
            a[2] = __float_as_uint(pp[4]);
            a[3] = __float_as_uint(pp[8 * SP + 4]);
            #pragma unroll
            for (int nt = 0; nt < 16; nt++) {
                uint32_t bfr[2];
                const float* vp = Vs + (k0 + lr) * VP + nt * 8 + lq;
                bfr[0] = __float_as_uint(vp[0]);
                bfr[1] = __float_as_uint(vp[4 * VP]);
                mma1688(oacc[nt], a, bfr);
            }
        }
        __syncthreads();
    }

    const float inv0 = 1.f / lrow0;
    const float inv1 = 1.f / lrow1;
    float* Og = g_attn + (size_t)(b * SS + qt * FBM + m0 + lq) * DM + qh * HD;
    #pragma unroll
    for (int nt = 0; nt < 16; nt++) {
        const int cb = nt * 8 + 2 * lr;
        *(float2*)(Og + cb) =
            make_float2(f2tf32f(oacc[nt][0] * inv0), f2tf32f(oacc[nt][1] * inv0));
        *(float2*)(Og + (size_t)8 * DM + cb) =
            make_float2(f2tf32f(oacc[nt][2] * inv1), f2tf32f(oacc[nt][3] * inv1));
    }
}

// ---------------------------------------------------------------------------
// Launch
// ---------------------------------------------------------------------------
extern "C" void kernel_launch(void* const* d_in, const int* in_sizes, int n_in,
                              void* d_out, int out_size)
{
    const float* hs   = (const float*)d_in[0];
    const float* cosb = (const float*)d_in[1];
    const float* sinb = (const float*)d_in[2];
    const float* Wqkv = (const float*)d_in[3];
    const float* Wout = (const float*)d_in[4];
    float* out = (float*)d_out;

    float *qkv_ptr, *attn_ptr, *rA, *rWq, *rWo;
    cudaGetSymbolAddress((void**)&qkv_ptr,  g_qkv);
    cudaGetSymbolAddress((void**)&attn_ptr, g_attn);
    cudaGetSymbolAddress((void**)&rA,  g_rA);
    cudaGetSymbolAddress((void**)&rWq, g_rWq);
    cudaGetSymbolAddress((void**)&rWo, g_rWo);

    cudaFuncSetAttribute(tf32gemm_k, cudaFuncAttributeMaxDynamicSharedMemorySize,
                         TF_SMEM_BYTES);
    cudaFuncSetAttribute(fattn_k, cudaFuncAttributeMaxDynamicSharedMemorySize,
                         FA_SMEM_BYTES);

    // 0) tf32 pre-rounding of all GEMM inputs
    round_k<<<592, 256>>>(hs,   rA,  (size_t)MROWS * DM / 4);
    round_k<<<592, 256>>>(Wqkv, rWq, (size_t)DM * QKVD / 4);
    round_k<<<592, 256>>>(Wout, rWo, (size_t)DM * DM / 4);

    // 1) QKV projection
    tf32gemm_k<<<dim3(QKVD / TBN, MROWS / TBM), 256, TF_SMEM_BYTES>>>(
        rA, rWq, qkv_ptr, MROWS, QKVD, DM);

    // 2) RoPE + tf32 rounding of Q/K/V
    rope_k<<<MROWS, 256>>>(cosb, sinb);

    // 3) Causal GQA flash attention (tf32 tensor cores)
    fattn_k<<<dim3(SS / FBM, NH, BB), 256, FA_SMEM_BYTES>>>();

    // 4) Output projection
    tf32gemm_k<<<dim3(DM / TBN, MROWS / TBM), 256, TF_SMEM_BYTES>>>(
        attn_ptr, rWo, out, MROWS, DM, DM);
}

// round 7
// speedup vs baseline: 3.8323x; 1.0143x over previous
#include <cuda_runtime.h>
#include <cuda_bf16.h>
#include <cstdint>
#include <math.h>

// Problem constants
#define BB      2
#define SS      2048
#define DM      4096
#define NH      32
#define NKV     8
#define HD      128
#define QKVD    6144          // (32 + 2*8) * 128
#define MROWS   4096          // B*S

// Scratch (allocation-free rule: __device__ globals)
__device__ float g_qkv [(size_t)MROWS * QKVD];   // qkv output (RoPE+rounding in place)
__device__ float g_attn[(size_t)MROWS * DM];     // attention output (tf32-rounded)
__device__ float g_rA  [(size_t)MROWS * DM];     // tf32-rounded hidden_states
__device__ float g_rWq [(size_t)DM * QKVD];      // tf32-rounded W_qkv
__device__ float g_rWo [(size_t)DM * DM];        // tf32-rounded W_out

__device__ __forceinline__ float f2tf32f(float x) {
    float r;
    asm("cvt.rna.tf32.f32 %0, %1;\n" : "=f"(r) : "f"(x));
    return r;
}
__device__ __forceinline__ float ex2f(float x) {
    float r;
    asm("ex2.approx.f32 %0, %1;\n" : "=f"(r) : "f"(x));
    return r;
}
__device__ __forceinline__ void cp_async16(uint32_t smem, const void* gmem) {
    asm volatile("cp.async.cg.shared.global [%0], [%1], 16;\n" :: "r"(smem), "l"(gmem));
}
__device__ __forceinline__ void mma1688(float* d, const uint32_t* a, const uint32_t* b) {
    asm volatile(
        "mma.sync.aligned.m16n8k8.row.col.f32.tf32.tf32.f32 "
        "{%0,%1,%2,%3}, {%4,%5,%6,%7}, {%8,%9}, {%0,%1,%2,%3};\n"
        : "+f"(d[0]), "+f"(d[1]), "+f"(d[2]), "+f"(d[3])
        : "r"(a[0]), "r"(a[1]), "r"(a[2]), "r"(a[3]), "r"(b[0]), "r"(b[1]));
}

// ---------------------------------------------------------------------------
// Elementwise tf32 rounding pass (float4 grid-stride)
// ---------------------------------------------------------------------------
__global__ void round_k(const float* __restrict__ in, float* __restrict__ out, size_t n4)
{
    for (size_t i = (size_t)blockIdx.x * blockDim.x + threadIdx.x; i < n4;
         i += (size_t)gridDim.x * blockDim.x) {
        float4 v = ((const float4*)in)[i];
        v.x = f2tf32f(v.x); v.y = f2tf32f(v.y);
        v.z = f2tf32f(v.z); v.w = f2tf32f(v.w);
        ((float4*)out)[i] = v;
    }
}

// ---------------------------------------------------------------------------
// TF32 tensor-core GEMM: C[M,N] = A[M,K] @ B[K,N]. Inputs PRE-ROUNDED to tf32.
// 128x128x32 tile, 256 thr, cp.async 3-stage, 2 CTAs/SM (regs capped 128).
// ---------------------------------------------------------------------------
#define TBM 128
#define TBN 128
#define TBK 32
#define APITCH 36
#define BPITCH 136
#define NSTAGE 3
#define AS_SZ (TBM * APITCH)
#define BS_SZ (TBK * BPITCH)
#define STAGE_SZ (AS_SZ + BS_SZ)
#define TF_SMEM_BYTES (NSTAGE * STAGE_SZ * 4)   // 107520 B; x2 CTAs = 215040 <= 227KB

__global__ __launch_bounds__(256, 2) void tf32gemm_k(
    const float* __restrict__ A, const float* __restrict__ B,
    float* __restrict__ C, int M, int N, int K)
{
    extern __shared__ __align__(16) float ts[];

    const int tid  = threadIdx.x;
    const int lane = tid & 31;
    const int wid  = tid >> 5;
    const int wm   = wid >> 2;
    const int wn   = wid & 3;
    const int bm   = blockIdx.y * TBM;
    const int bn   = blockIdx.x * TBN;
    const int lq   = lane >> 2;
    const int lr   = lane & 3;

    const int a_r[4]  = { tid >> 3, (tid + 256) >> 3, (tid + 512) >> 3, (tid + 768) >> 3 };
    const int a_c4    = (tid & 7) << 2;
    const int b_k[4]  = { tid >> 5, (tid + 256) >> 5, (tid + 512) >> 5, (tid + 768) >> 5 };
    const int b_n4    = (tid & 31) << 2;

    float acc[4][4][4];
    #pragma unroll
    for (int i = 0; i < 4; i++)
        #pragma unroll
        for (int j = 0; j < 4; j++)
            #pragma unroll
            for (int c = 0; c < 4; c++) acc[i][j][c] = 0.f;

    const int KT = K / TBK;

    auto issue = [&](int kt, int buf) {
        float* sA = ts + buf * STAGE_SZ;
        float* sB = sA + AS_SZ;
        const float* Ag = A + (size_t)bm * K + kt * TBK;
        const float* Bg = B + (size_t)(kt * TBK) * N + bn;
        uint32_t sAu = (uint32_t)__cvta_generic_to_shared(sA);
        uint32_t sBu = (uint32_t)__cvta_generic_to_shared(sB);
        #pragma unroll
        for (int i = 0; i < 4; i++)
            cp_async16(sAu + (uint32_t)(a_r[i] * APITCH + a_c4) * 4,
                       Ag + (size_t)a_r[i] * K + a_c4);
        #pragma unroll
        for (int i = 0; i < 4; i++)
            cp_async16(sBu + (uint32_t)(b_k[i] * BPITCH + b_n4) * 4,
                       Bg + (size_t)b_k[i] * N + b_n4);
        asm volatile("cp.async.commit_group;\n");
    };

    issue(0, 0);
    issue(1, 1);

    for (int kt = 0; kt < KT; kt++) {
        asm volatile("cp.async.wait_group 1;\n");
        __syncthreads();

        const int nk = kt + 2;
        if (nk < KT) issue(nk, nk % NSTAGE);
        else         asm volatile("cp.async.commit_group;\n");   // keep count in step

        const float* sA = ts + (kt % NSTAGE) * STAGE_SZ;
        const float* sB = sA + AS_SZ;

        #pragma unroll
        for (int ks = 0; ks < 4; ks++) {
            const int k0 = ks * 8;
            uint32_t af[4][4], bf[4][2];
            #pragma unroll
            for (int mt = 0; mt < 4; mt++) {
                const float* p = sA + (wm * 64 + mt * 16 + lq) * APITCH + k0 + lr;
                af[mt][0] = __float_as_uint(p[0]);
                af[mt][1] = __float_as_uint(p[8 * APITCH]);
                af[mt][2] = __float_as_uint(p[4]);
                af[mt][3] = __float_as_uint(p[8 * APITCH + 4]);
            }
            #pragma unroll
            for (int nt = 0; nt < 4; nt++) {
                const float* p = sB + (k0 + lr) * BPITCH + wn * 32 + nt * 8 + lq;
                bf[nt][0] = __float_as_uint(p[0]);
                bf[nt][1] = __float_as_uint(p[4 * BPITCH]);
            }
            #pragma unroll
            for (int mt = 0; mt < 4; mt++)
                #pragma unroll
                for (int nt = 0; nt < 4; nt++)
                    mma1688(acc[mt][nt], af[mt], bf[nt]);
        }
        __syncthreads();
    }

    #pragma unroll
    for (int mt = 0; mt < 4; mt++) {
        #pragma unroll
        for (int nt = 0; nt < 4; nt++) {
            const int row = bm + wm * 64 + mt * 16 + lq;
            const int col = bn + wn * 32 + nt * 8 + 2 * lr;
            float* c0 = C + (size_t)row * N + col;
            float* c1 = C + (size_t)(row + 8) * N + col;
            *(float2*)c0 = make_float2(acc[mt][nt][0], acc[mt][nt][1]);
            *(float2*)c1 = make_float2(acc[mt][nt][2], acc[mt][nt][3]);
        }
    }
}

// ---------------------------------------------------------------------------
// RoPE in place on Q/K of g_qkv + tf32 rounding of Q, K, AND V.
// ---------------------------------------------------------------------------
__global__ void rope_k(const float* __restrict__ cost, const float* __restrict__ sint)
{
    const int row = blockIdx.x;            // 0..4095
    const int s   = row & (SS - 1);
    float* q = g_qkv + (size_t)row * QKVD;

    const int NROPE = (NH + NKV) * 64;
    const int NV    = NKV * HD;
    for (int p = threadIdx.x; p < NROPE + NV; p += blockDim.x) {
        if (p < NROPE) {
            const int h = p >> 6;
            const int d = p & 63;
            const int base = h * HD;
            const float c  = cost[s * HD + d];
            const float sn = sint[s * HD + d];
            const float x1 = q[base + d];
            const float x2 = q[base + d + 64];
            q[base + d]      = f2tf32f(x1 * c - x2 * sn);
            q[base + d + 64] = f2tf32f(x2 * c + x1 * sn);
        } else {
            const int idx = (NH + NKV) * HD + (p - NROPE);
            q[idx] = f2tf32f(q[idx]);
        }
    }
}

// ---------------------------------------------------------------------------
// Flash attention, tf32 mma.sync, cp.async pipelined K/V loads.
// K double-buffered; V single-buffered but overlapped with QK+softmax.
// ---------------------------------------------------------------------------
#define FBM 128
#define FBN 64
#define QP  132
#define KP  132
#define VP  136
#define SP  68
#define FA_SMEM_FLOATS (FBM*QP + 2*FBN*KP + FBN*VP + FBM*SP)
#define FA_SMEM_BYTES  (FA_SMEM_FLOATS * 4)   // 204800 B

__global__ __launch_bounds__(256, 1) void fattn_k()
{
    extern __shared__ __align__(16) float sm[];
    float* Qs  = sm;                          // [128][QP]
    float* Kb0 = Qs  + FBM * QP;              // [64][KP]
    float* Kb1 = Kb0 + FBN * KP;              // [64][KP]
    float* Vs  = Kb1 + FBN * KP;              // [64][VP]
    float* Ps  = Vs  + FBN * VP;              // [128][SP]

    const uint32_t k0u = (uint32_t)__cvta_generic_to_shared(Kb0);
    const uint32_t k1u = (uint32_t)__cvta_generic_to_shared(Kb1);
    const uint32_t vsu = (uint32_t)__cvta_generic_to_shared(Vs);

    const int qt  = blockIdx.x;
    const int qh  = blockIdx.y;
    const int b   = blockIdx.z;
    const int kh  = qh >> 2;
    const int tid = threadIdx.x;
    const int lane = tid & 31;
    const int w   = tid >> 5;
    const int lq  = lane >> 2;
    const int lr  = lane & 3;
    const int m0  = w * 16;

    const float* Qg = g_qkv + (size_t)(b * SS + qt * FBM) * QKVD + qh * HD;
    const float* Kg = g_qkv + (size_t)(b * SS) * QKVD + NH * HD + kh * HD;
    const float* Vg = g_qkv + (size_t)(b * SS) * QKVD + (NH + NKV) * HD + kh * HD;

    // scale * log2(e): softmax computed in base-2 domain
    const float scale2 = 0.08838834764831845f * 1.4426950408889634f;

    auto cpK = [&](int kt2, uint32_t dst) {
        #pragma unroll
        for (int q = 0; q < 8; q++) {
            const int i = q * 256 + tid;          // 2048 16B chunks
            const int r = i >> 5, c = (i & 31) << 2;
            cp_async16(dst + (uint32_t)(r * KP + c) * 4,
                       Kg + (size_t)(kt2 * FBN + r) * QKVD + c);
        }
        asm volatile("cp.async.commit_group;\n");
    };
    auto cpV = [&](int kt2) {
        #pragma unroll
        for (int q = 0; q < 8; q++) {
            const int i = q * 256 + tid;
            const int r = i >> 5, c = (i & 31) << 2;
            cp_async16(vsu + (uint32_t)(r * VP + c) * 4,
                       Vg + (size_t)(kt2 * FBN + r) * QKVD + c);
        }
        asm volatile("cp.async.commit_group;\n");
    };

    // Load Q (blocking) + prefetch K tile 0
    for (int i = tid; i < FBM * (HD / 4); i += 256) {
        const int r = i >> 5, c4 = (i & 31) << 2;
        *(float4*)&Qs[r * QP + c4] = *(const float4*)(Qg + (size_t)r * QKVD + c4);
    }
    cpK(0, k0u);

    float oacc[16][4];
    #pragma unroll
    for (int i = 0; i < 16; i++)
        #pragma unroll
        for (int c = 0; c < 4; c++) oacc[i][c] = 0.f;
    float mrow0 = -1e30f, mrow1 = -1e30f;
    float lrow0 = 0.f,    lrow1 = 0.f;

    const int ktmax = 2 * qt + 2;
    for (int kt2 = 0; kt2 < ktmax; kt2++) {
        cpV(kt2);                                        // overlaps with QK+softmax
        asm volatile("cp.async.wait_group 1;\n");        // K_cur complete
        __syncthreads();                                 // K (and Q on iter 0) visible

        const float* Kc = (kt2 & 1) ? Kb1 : Kb0;

        // S = Q K^T
        float sacc[8][4];
        #pragma unroll
        for (int i = 0; i < 8; i++)
            #pragma unroll
            for (int c = 0; c < 4; c++) sacc[i][c] = 0.f;

        #pragma unroll
        for (int k = 0; k < 16; k++) {
            const int k0 = k * 8;
            uint32_t a[4];
            const float* qp = Qs + (m0 + lq) * QP + k0 + lr;
            a[0] = __float_as_uint(qp[0]);
            a[1] = __float_as_uint(qp[8 * QP]);
            a[2] = __float_as_uint(qp[4]);
            a[3] = __float_as_uint(qp[8 * QP + 4]);
            #pragma unroll
            for (int nt = 0; nt < 8; nt++) {
                uint32_t bfr[2];
                const float* kp = Kc + (nt * 8 + lq) * KP + k0 + lr;
                bfr[0] = __float_as_uint(kp[0]);
                bfr[1] = __float_as_uint(kp[4]);
                mma1688(sacc[nt], a, bfr);
            }
        }

        const bool need_mask = (kt2 >= 2 * qt);
        const int r0 = qt * FBM + m0 + lq;
        const int r1 = r0 + 8;
        #pragma unroll
        for (int nt = 0; nt < 8; nt++) {
            const int colb = kt2 * FBN + nt * 8 + 2 * lr;
            #pragma unroll
            for (int c = 0; c < 4; c++) sacc[nt][c] *= scale2;
            if (need_mask) {
                if (colb     > r0) sacc[nt][0] = -1e30f;
                if (colb + 1 > r0) sacc[nt][1] = -1e30f;
                if (colb     > r1) sacc[nt][2] = -1e30f;
                if (colb + 1 > r1) sacc[nt][3] = -1e30f;
            }
        }

        // Online softmax in base-2 domain
        float mx0 = -1e30f, mx1 = -1e30f;
        #pragma unroll
        for (int nt = 0; nt < 8; nt++) {
            mx0 = fmaxf(mx0, fmaxf(sacc[nt][0], sacc[nt][1]));
            mx1 = fmaxf(mx1, fmaxf(sacc[nt][2], sacc[nt][3]));
        }
        mx0 = fmaxf(mx0, __shfl_xor_sync(0xffffffffu, mx0, 1));
        mx0 = fmaxf(mx0, __shfl_xor_sync(0xffffffffu, mx0, 2));
        mx1 = fmaxf(mx1, __shfl_xor_sync(0xffffffffu, mx1, 1));
        mx1 = fmaxf(mx1, __shfl_xor_sync(0xffffffffu, mx1, 2));

        const float mn0 = fmaxf(mrow0, mx0);
        const float mn1 = fmaxf(mrow1, mx1);
        const float scl0 = ex2f(mrow0 - mn0);
        const float scl1 = ex2f(mrow1 - mn1);
        mrow0 = mn0; mrow1 = mn1;

        float rs0 = 0.f, rs1 = 0.f;
        #pragma unroll
        for (int nt = 0; nt < 8; nt++) {
            float p0 = f2tf32f(ex2f(sacc[nt][0] - mn0));
            float p1 = f2tf32f(ex2f(sacc[nt][1] - mn0));
            float p2 = f2tf32f(ex2f(sacc[nt][2] - mn1));
            float p3 = f2tf32f(ex2f(sacc[nt][3] - mn1));
            rs0 += p0 + p1;
            rs1 += p2 + p3;
            const int cb = nt * 8 + 2 * lr;
            *(float2*)&Ps[(m0 + lq) * SP + cb]     = make_float2(p0, p1);
            *(float2*)&Ps[(m0 + lq + 8) * SP + cb] = make_float2(p2, p3);
        }
        rs0 += __shfl_xor_sync(0xffffffffu, rs0, 1);
        rs0 += __shfl_xor_sync(0xffffffffu, rs0, 2);
        rs1 += __shfl_xor_sync(0xffffffffu, rs1, 1);
        rs1 += __shfl_xor_sync(0xffffffffu, rs1, 2);
        lrow0 = lrow0 * scl0 + rs0;
        lrow1 = lrow1 * scl1 + rs1;

        #pragma unroll
        for (int nt = 0; nt < 16; nt++) {
            oacc[nt][0] *= scl0; oacc[nt][1] *= scl0;
            oacc[nt][2] *= scl1; oacc[nt][3] *= scl1;
        }
        __syncwarp();   // this warp's P rows complete

        // Prefetch next K tile (overlaps with PV)
        if (kt2 + 1 < ktmax) cpK(kt2 + 1, ((kt2 + 1) & 1) ? k1u : k0u);
        else asm volatile("cp.async.commit_group;\n");

        asm volatile("cp.async.wait_group 1;\n");        // V_cur complete
        __syncthreads();                                 // V visible to all

        // O += P V
        #pragma unroll
        for (int k = 0; k < 8; k++) {
            const int k0 = k * 8;
            uint32_t a[4];
            const float* pp = Ps + (m0 + lq) * SP + k0 + lr;
            a[0] = __float_as_uint(pp[0]);
            a[1] = __float_as_uint(pp[8 * SP]);
            a[2] = __float_as_uint(pp[4]);
            a[3] = __float_as_uint(pp[8 * SP + 4]);
            #pragma unroll
            for (int nt = 0; nt < 16; nt++) {
                uint32_t bfr[2];
                const float* vp = Vs + (k0 + lr) * VP + nt * 8 + lq;
                bfr[0] = __float_as_uint(vp[0]);
                bfr[1] = __float_as_uint(vp[4 * VP]);
                mma1688(oacc[nt], a, bfr);
            }
        }
        __syncthreads();   // protect Vs/Ps before next iteration overwrites
    }

    const float inv0 = 1.f / lrow0;
    const float inv1 = 1.f / lrow1;
    float* Og = g_attn + (size_t)(b * SS + qt * FBM + m0 + lq) * DM + qh * HD;
    #pragma unroll
    for (int nt = 0; nt < 16; nt++) {
        const int cb = nt * 8 + 2 * lr;
        *(float2*)(Og + cb) =
            make_float2(f2tf32f(oacc[nt][0] * inv0), f2tf32f(oacc[nt][1] * inv0));
        *(float2*)(Og + (size_t)8 * DM + cb) =
            make_float2(f2tf32f(oacc[nt][2] * inv1), f2tf32f(oacc[nt][3] * inv1));
    }
}

// ---------------------------------------------------------------------------
// Launch
// ---------------------------------------------------------------------------
extern "C" void kernel_launch(void* const* d_in, const int* in_sizes, int n_in,
                              void* d_out, int out_size)
{
    const float* hs   = (const float*)d_in[0];
    const float* cosb = (const float*)d_in[1];
    const float* sinb = (const float*)d_in[2];
    const float* Wqkv = (const float*)d_in[3];
    const float* Wout = (const float*)d_in[4];
    float* out = (float*)d_out;

    float *qkv_ptr, *attn_ptr, *rA, *rWq, *rWo;
    cudaGetSymbolAddress((void**)&qkv_ptr,  g_qkv);
    cudaGetSymbolAddress((void**)&attn_ptr, g_attn);
    cudaGetSymbolAddress((void**)&rA,  g_rA);
    cudaGetSymbolAddress((void**)&rWq, g_rWq);
    cudaGetSymbolAddress((void**)&rWo, g_rWo);

    cudaFuncSetAttribute(tf32gemm_k, cudaFuncAttributeMaxDynamicSharedMemorySize,
                         TF_SMEM_BYTES);
    cudaFuncSetAttribute(fattn_k, cudaFuncAttributeMaxDynamicSharedMemorySize,
                         FA_SMEM_BYTES);

    // 0) tf32 pre-rounding of all GEMM inputs
    round_k<<<592, 256>>>(hs,   rA,  (size_t)MROWS * DM / 4);
    round_k<<<592, 256>>>(Wqkv, rWq, (size_t)DM * QKVD / 4);
    round_k<<<592, 256>>>(Wout, rWo, (size_t)DM * DM / 4);

    // 1) QKV projection
    tf32gemm_k<<<dim3(QKVD / TBN, MROWS / TBM), 256, TF_SMEM_BYTES>>>(
        rA, rWq, qkv_ptr, MROWS, QKVD, DM);

    // 2) RoPE + tf32 rounding of Q/K/V
    rope_k<<<MROWS, 256>>>(cosb, sinb);

    // 3) Causal GQA flash attention (pipelined)
    fattn_k<<<dim3(SS / FBM, NH, BB), 256, FA_SMEM_BYTES>>>();

    // 4) Output projection
    tf32gemm_k<<<dim3(DM / TBN, MROWS / TBM), 256, TF_SMEM_BYTES>>>(
        attn_ptr, rWo, out, MROWS, DM, DM);
}

// round 8
// speedup vs baseline: 4.1563x; 1.0845x over previous
#include <cuda_runtime.h>
#include <cuda_bf16.h>
#include <cstdint>
#include <math.h>

// Problem constants
#define BB      2
#define SS      2048
#define DM      4096
#define NH      32
#define NKV     8
#define HD      128
#define QKVD    6144          // (32 + 2*8) * 128
#define MROWS   4096          // B*S

// Scratch (allocation-free rule: __device__ globals)
__device__ float g_qkv [(size_t)MROWS * QKVD];   // qkv output (RoPE+rounding in place)
__device__ float g_attn[(size_t)MROWS * DM];     // attention output (tf32-rounded)
__device__ float g_rA  [(size_t)MROWS * DM];     // tf32-rounded hidden_states
__device__ float g_rWq [(size_t)DM * QKVD];      // tf32-rounded W_qkv, TRANSPOSED [N][K]
__device__ float g_rWo [(size_t)DM * DM];        // tf32-rounded W_out,  TRANSPOSED [N][K]

__device__ __forceinline__ float f2tf32f(float x) {
    float r;
    asm("cvt.rna.tf32.f32 %0, %1;\n" : "=f"(r) : "f"(x));
    return r;
}
__device__ __forceinline__ float ex2f(float x) {
    float r;
    asm("ex2.approx.f32 %0, %1;\n" : "=f"(r) : "f"(x));
    return r;
}
__device__ __forceinline__ void cp_async16(uint32_t smem, const void* gmem) {
    asm volatile("cp.async.cg.shared.global [%0], [%1], 16;\n" :: "r"(smem), "l"(gmem));
}
__device__ __forceinline__ void ldsm4(uint32_t& r0, uint32_t& r1, uint32_t& r2,
                                      uint32_t& r3, uint32_t addr) {
    asm volatile("ldmatrix.sync.aligned.m8n8.x4.shared.b16 {%0,%1,%2,%3}, [%4];"
                 : "=r"(r0), "=r"(r1), "=r"(r2), "=r"(r3) : "r"(addr));
}
__device__ __forceinline__ void mma1688(float* d, const uint32_t* a,
                                        uint32_t b0, uint32_t b1) {
    asm volatile(
        "mma.sync.aligned.m16n8k8.row.col.f32.tf32.tf32.f32 "
        "{%0,%1,%2,%3}, {%4,%5,%6,%7}, {%8,%9}, {%0,%1,%2,%3};\n"
        : "+f"(d[0]), "+f"(d[1]), "+f"(d[2]), "+f"(d[3])
        : "r"(a[0]), "r"(a[1]), "r"(a[2]), "r"(a[3]), "r"(b0), "r"(b1));
}

// ---------------------------------------------------------------------------
// Elementwise tf32 rounding pass (float4 grid-stride)
// ---------------------------------------------------------------------------
__global__ void round_k(const float* __restrict__ in, float* __restrict__ out, size_t n4)
{
    for (size_t i = (size_t)blockIdx.x * blockDim.x + threadIdx.x; i < n4;
         i += (size_t)gridDim.x * blockDim.x) {
        float4 v = ((const float4*)in)[i];
        v.x = f2tf32f(v.x); v.y = f2tf32f(v.y);
        v.z = f2tf32f(v.z); v.w = f2tf32f(v.w);
        ((float4*)out)[i] = v;
    }
}

// ---------------------------------------------------------------------------
// Tiled transpose + tf32 round: in[K][N] row-major -> out[N][K] row-major
// ---------------------------------------------------------------------------
__global__ void tround_k(const float* __restrict__ in, float* __restrict__ out,
                         int K, int N)
{
    __shared__ float t[32][33];
    const int k0 = blockIdx.y * 32, n0 = blockIdx.x * 32;
    const int x = threadIdx.x, y = threadIdx.y;   // block (32, 8)
    #pragma unroll
    for (int i = 0; i < 32; i += 8)
        t[y + i][x] = in[(size_t)(k0 + y + i) * N + n0 + x];
    __syncthreads();
    #pragma unroll
    for (int i = 0; i < 32; i += 8)
        out[(size_t)(n0 + y + i) * K + k0 + x] = f2tf32f(t[x][y + i]);
}

// ---------------------------------------------------------------------------
// TF32 tensor-core GEMM: C[M,N] = A[M,K] @ Bt[N,K]^T (both row-major,
// pre-rounded). 128x128x32 tile, 256 thr, cp.async 3-stage, 2 CTAs/SM,
// ldmatrix fragment loads.
// ---------------------------------------------------------------------------
#define TBM 128
#define TBN 128
#define TBK 32
#define TPITCH 36
#define NSTAGE 3
#define TILE_SZ (128 * TPITCH)            // 4608 floats (A or B)
#define STAGE_SZ (2 * TILE_SZ)            // 9216 floats
#define TF_SMEM_BYTES (NSTAGE * STAGE_SZ * 4)   // 110592 B; x2 CTAs fits 227KB

__global__ __launch_bounds__(256, 2) void tf32gemm_k(
    const float* __restrict__ A, const float* __restrict__ Bt,
    float* __restrict__ C, int M, int N, int K)
{
    extern __shared__ __align__(16) float ts[];
    const uint32_t tsu = (uint32_t)__cvta_generic_to_shared(ts);

    const int tid  = threadIdx.x;
    const int lane = tid & 31;
    const int wid  = tid >> 5;
    const int wm   = wid >> 2;            // 0..1 -> 64 rows
    const int wn   = wid & 3;             // 0..3 -> 32 cols
    const int bm   = blockIdx.y * TBM;
    const int bn   = blockIdx.x * TBN;
    const int lq   = lane >> 2;
    const int lr   = lane & 3;

    // ldmatrix per-lane tile coords
    const int rA_ld = ((lane >> 3) & 1) * 8 + (lane & 7);   // A/P-style frag
    const int cA_ld = (lane >> 4) * 4;
    const int rB_ld = ((lane >> 4) & 1) * 8 + (lane & 7);   // B-style frag
    const int cB_ld = ((lane >> 3) & 1) * 4;

    // cp.async coords: 128 rows x 32 floats per tile, 4 chunks/thread
    const int g_r[4] = { tid >> 3, (tid + 256) >> 3, (tid + 512) >> 3, (tid + 768) >> 3 };
    const int g_c4   = (tid & 7) << 2;

    float acc[4][4][4];
    #pragma unroll
    for (int i = 0; i < 4; i++)
        #pragma unroll
        for (int j = 0; j < 4; j++)
            #pragma unroll
            for (int c = 0; c < 4; c++) acc[i][j][c] = 0.f;

    const int KT = K / TBK;

    auto issue = [&](int kt, int buf) {
        const uint32_t sAu = tsu + (uint32_t)(buf * STAGE_SZ) * 4;
        const uint32_t sBu = sAu + (uint32_t)TILE_SZ * 4;
        const float* Ag = A  + (size_t)bm * K + kt * TBK;
        const float* Bg = Bt + (size_t)bn * K + kt * TBK;
        #pragma unroll
        for (int i = 0; i < 4; i++) {
            cp_async16(sAu + (uint32_t)(g_r[i] * TPITCH + g_c4) * 4,
                       Ag + (size_t)g_r[i] * K + g_c4);
            cp_async16(sBu + (uint32_t)(g_r[i] * TPITCH + g_c4) * 4,
                       Bg + (size_t)g_r[i] * K + g_c4);
        }
        asm volatile("cp.async.commit_group;\n");
    };

    issue(0, 0);
    issue(1, 1);

    for (int kt = 0; kt < KT; kt++) {
        asm volatile("cp.async.wait_group 1;\n");
        __syncthreads();

        const int nk = kt + 2;
        if (nk < KT) issue(nk, nk % NSTAGE);
        else         asm volatile("cp.async.commit_group;\n");

        const uint32_t sAu = tsu + (uint32_t)((kt % NSTAGE) * STAGE_SZ) * 4;
        const uint32_t sBu = sAu + (uint32_t)TILE_SZ * 4;

        #pragma unroll
        for (int ks = 0; ks < 4; ks++) {
            const int k0 = ks * 8;
            uint32_t af[4][4], bf[2][4];
            #pragma unroll
            for (int mt = 0; mt < 4; mt++)
                ldsm4(af[mt][0], af[mt][1], af[mt][2], af[mt][3],
                      sAu + (uint32_t)((wm * 64 + mt * 16 + rA_ld) * TPITCH
                                       + cA_ld + k0) * 4);
            #pragma unroll
            for (int p = 0; p < 2; p++)
                ldsm4(bf[p][0], bf[p][1], bf[p][2], bf[p][3],
                      sBu + (uint32_t)((wn * 32 + p * 16 + rB_ld) * TPITCH
                                       + cB_ld + k0) * 4);
            #pragma unroll
            for (int mt = 0; mt < 4; mt++)
                #pragma unroll
                for (int nt = 0; nt < 4; nt++)
                    mma1688(acc[mt][nt], af[mt],
                            bf[nt >> 1][(nt & 1) * 2], bf[nt >> 1][(nt & 1) * 2 + 1]);
        }
        __syncthreads();
    }

    #pragma unroll
    for (int mt = 0; mt < 4; mt++) {
        #pragma unroll
        for (int nt = 0; nt < 4; nt++) {
            const int row = bm + wm * 64 + mt * 16 + lq;
            const int col = bn + wn * 32 + nt * 8 + 2 * lr;
            float* c0 = C + (size_t)row * N + col;
            float* c1 = C + (size_t)(row + 8) * N + col;
            *(float2*)c0 = make_float2(acc[mt][nt][0], acc[mt][nt][1]);
            *(float2*)c1 = make_float2(acc[mt][nt][2], acc[mt][nt][3]);
        }
    }
}

// ---------------------------------------------------------------------------
// RoPE in place on Q/K of g_qkv + tf32 rounding of Q, K, AND V.
// ---------------------------------------------------------------------------
__global__ void rope_k(const float* __restrict__ cost, const float* __restrict__ sint)
{
    const int row = blockIdx.x;            // 0..4095
    const int s   = row & (SS - 1);
    float* q = g_qkv + (size_t)row * QKVD;

    const int NROPE = (NH + NKV) * 64;
    const int NV    = NKV * HD;
    for (int p = threadIdx.x; p < NROPE + NV; p += blockDim.x) {
        if (p < NROPE) {
            const int h = p >> 6;
            const int d = p & 63;
            const int base = h * HD;
            const float c  = cost[s * HD + d];
            const float sn = sint[s * HD + d];
            const float x1 = q[base + d];
            const float x2 = q[base + d + 64];
            q[base + d]      = f2tf32f(x1 * c - x2 * sn);
            q[base + d + 64] = f2tf32f(x2 * c + x1 * sn);
        } else {
            const int idx = (NH + NKV) * HD + (p - NROPE);
            q[idx] = f2tf32f(q[idx]);
        }
    }
}

// ---------------------------------------------------------------------------
// Flash attention, tf32 mma.sync, cp.async pipelined K/V, ldmatrix Q/K/P frags.
// ---------------------------------------------------------------------------
#define FBM 128
#define FBN 64
#define QP  132
#define KP  132
#define VP  136
#define SP  68
#define FA_SMEM_FLOATS (FBM*QP + 2*FBN*KP + FBN*VP + FBM*SP)
#define FA_SMEM_BYTES  (FA_SMEM_FLOATS * 4)   // 204800 B

__global__ __launch_bounds__(256, 1) void fattn_k()
{
    extern __shared__ __align__(16) float sm[];
    float* Qs  = sm;                          // [128][QP]
    float* Kb0 = Qs  + FBM * QP;              // [64][KP]
    float* Kb1 = Kb0 + FBN * KP;              // [64][KP]
    float* Vs  = Kb1 + FBN * KP;              // [64][VP]
    float* Ps  = Vs  + FBN * VP;              // [128][SP]

    const uint32_t qsu = (uint32_t)__cvta_generic_to_shared(Qs);
    const uint32_t k0u = (uint32_t)__cvta_generic_to_shared(Kb0);
    const uint32_t k1u = (uint32_t)__cvta_generic_to_shared(Kb1);
    const uint32_t vsu = (uint32_t)__cvta_generic_to_shared(Vs);
    const uint32_t psu = (uint32_t)__cvta_generic_to_shared(Ps);

    const int qt  = blockIdx.x;
    const int qh  = blockIdx.y;
    const int b   = blockIdx.z;
    const int kh  = qh >> 2;
    const int tid = threadIdx.x;
    const int lane = tid & 31;
    const int w   = tid >> 5;
    const int lq  = lane >> 2;
    const int lr  = lane & 3;
    const int m0  = w * 16;

    const int rA_ld = ((lane >> 3) & 1) * 8 + (lane & 7);
    const int cA_ld = (lane >> 4) * 4;
    const int rB_ld = ((lane >> 4) & 1) * 8 + (lane & 7);
    const int cB_ld = ((lane >> 3) & 1) * 4;

    const float* Qg = g_qkv + (size_t)(b * SS + qt * FBM) * QKVD + qh * HD;
    const float* Kg = g_qkv + (size_t)(b * SS) * QKVD + NH * HD + kh * HD;
    const float* Vg = g_qkv + (size_t)(b * SS) * QKVD + (NH + NKV) * HD + kh * HD;

    const float scale2 = 0.08838834764831845f * 1.4426950408889634f;

    auto cpK = [&](int kt2, uint32_t dst) {
        #pragma unroll
        for (int q = 0; q < 8; q++) {
            const int i = q * 256 + tid;
            const int r = i >> 5, c = (i & 31) << 2;
            cp_async16(dst + (uint32_t)(r * KP + c) * 4,
                       Kg + (size_t)(kt2 * FBN + r) * QKVD + c);
        }
        asm volatile("cp.async.commit_group;\n");
    };
    auto cpV = [&](int kt2) {
        #pragma unroll
        for (int q = 0; q < 8; q++) {
            const int i = q * 256 + tid;
            const int r = i >> 5, c = (i & 31) << 2;
            cp_async16(vsu + (uint32_t)(r * VP + c) * 4,
                       Vg + (size_t)(kt2 * FBN + r) * QKVD + c);
        }
        asm volatile("cp.async.commit_group;\n");
    };

    for (int i = tid; i < FBM * (HD / 4); i += 256) {
        const int r = i >> 5, c4 = (i & 31) << 2;
        *(float4*)&Qs[r * QP + c4] = *(const float4*)(Qg + (size_t)r * QKVD + c4);
    }
    cpK(0, k0u);

    float oacc[16][4];
    #pragma unroll
    for (int i = 0; i < 16; i++)
        #pragma unroll
        for (int c = 0; c < 4; c++) oacc[i][c] = 0.f;
    float mrow0 = -1e30f, mrow1 = -1e30f;
    float lrow0 = 0.f,    lrow1 = 0.f;

    const int ktmax = 2 * qt + 2;
    for (int kt2 = 0; kt2 < ktmax; kt2++) {
        cpV(kt2);
        asm volatile("cp.async.wait_group 1;\n");    // K_cur complete
        __syncthreads();

        const uint32_t kcu = (kt2 & 1) ? k1u : k0u;

        // S = Q K^T (ldmatrix fragments)
        float sacc[8][4];
        #pragma unroll
        for (int i = 0; i < 8; i++)
            #pragma unroll
            for (int c = 0; c < 4; c++) sacc[i][c] = 0.f;

        #pragma unroll
        for (int k = 0; k < 16; k++) {
            const int k0 = k * 8;
            uint32_t a[4], bf[4][4];
            ldsm4(a[0], a[1], a[2], a[3],
                  qsu + (uint32_t)((m0 + rA_ld) * QP + cA_ld + k0) * 4);
            #pragma unroll
            for (int p = 0; p < 4; p++)
                ldsm4(bf[p][0], bf[p][1], bf[p][2], bf[p][3],
                      kcu + (uint32_t)((p * 16 + rB_ld) * KP + cB_ld + k0) * 4);
            #pragma unroll
            for (int nt = 0; nt < 8; nt++)
                mma1688(sacc[nt], a,
                        bf[nt >> 1][(nt & 1) * 2], bf[nt >> 1][(nt & 1) * 2 + 1]);
        }

        const bool need_mask = (kt2 >= 2 * qt);
        const int r0 = qt * FBM + m0 + lq;
        const int r1 = r0 + 8;
        #pragma unroll
        for (int nt = 0; nt < 8; nt++) {
            const int colb = kt2 * FBN + nt * 8 + 2 * lr;
            #pragma unroll
            for (int c = 0; c < 4; c++) sacc[nt][c] *= scale2;
            if (need_mask) {
                if (colb     > r0) sacc[nt][0] = -1e30f;
                if (colb + 1 > r0) sacc[nt][1] = -1e30f;
                if (colb     > r1) sacc[nt][2] = -1e30f;
                if (colb + 1 > r1) sacc[nt][3] = -1e30f;
            }
        }

        // Online softmax (base-2 domain)
        float mx0 = -1e30f, mx1 = -1e30f;
        #pragma unroll
        for (int nt = 0; nt < 8; nt++) {
            mx0 = fmaxf(mx0, fmaxf(sacc[nt][0], sacc[nt][1]));
            mx1 = fmaxf(mx1, fmaxf(sacc[nt][2], sacc[nt][3]));
        }
        mx0 = fmaxf(mx0, __shfl_xor_sync(0xffffffffu, mx0, 1));
        mx0 = fmaxf(mx0, __shfl_xor_sync(0xffffffffu, mx0, 2));
        mx1 = fmaxf(mx1, __shfl_xor_sync(0xffffffffu, mx1, 1));
        mx1 = fmaxf(mx1, __shfl_xor_sync(0xffffffffu, mx1, 2));

        const float mn0 = fmaxf(mrow0, mx0);
        const float mn1 = fmaxf(mrow1, mx1);
        const float scl0 = ex2f(mrow0 - mn0);
        const float scl1 = ex2f(mrow1 - mn1);
        mrow0 = mn0; mrow1 = mn1;

        float rs0 = 0.f, rs1 = 0.f;
        #pragma unroll
        for (int nt = 0; nt < 8; nt++) {
            float p0 = f2tf32f(ex2f(sacc[nt][0] - mn0));
            float p1 = f2tf32f(ex2f(sacc[nt][1] - mn0));
            float p2 = f2tf32f(ex2f(sacc[nt][2] - mn1));
            float p3 = f2tf32f(ex2f(sacc[nt][3] - mn1));
            rs0 += p0 + p1;
            rs1 += p2 + p3;
            const int cb = nt * 8 + 2 * lr;
            *(float2*)&Ps[(m0 + lq) * SP + cb]     = make_float2(p0, p1);
            *(float2*)&Ps[(m0 + lq + 8) * SP + cb] = make_float2(p2, p3);
        }
        rs0 += __shfl_xor_sync(0xffffffffu, rs0, 1);
        rs0 += __shfl_xor_sync(0xffffffffu, rs0, 2);
        rs1 += __shfl_xor_sync(0xffffffffu, rs1, 1);
        rs1 += __shfl_xor_sync(0xffffffffu, rs1, 2);
        lrow0 = lrow0 * scl0 + rs0;
        lrow1 = lrow1 * scl1 + rs1;

        #pragma unroll
        for (int nt = 0; nt < 16; nt++) {
            oacc[nt][0] *= scl0; oacc[nt][1] *= scl0;
            oacc[nt][2] *= scl1; oacc[nt][3] *= scl1;
        }
        __syncwarp();   // this warp's P rows complete before ldmatrix reads

        if (kt2 + 1 < ktmax) cpK(kt2 + 1, ((kt2 + 1) & 1) ? k1u : k0u);
        else asm volatile("cp.async.commit_group;\n");

        asm volatile("cp.async.wait_group 1;\n");    // V_cur complete
        __syncthreads();

        // O += P V (P via ldmatrix, V scalar)
        #pragma unroll
        for (int k = 0; k < 8; k++) {
            const int k0 = k * 8;
            uint32_t a[4];
            ldsm4(a[0], a[1], a[2], a[3],
                  psu + (uint32_t)((m0 + rA_ld) * SP + cA_ld + k0) * 4);
            #pragma unroll
            for (int nt = 0; nt < 16; nt++) {
                const float* vp = Vs + (k0 + lr) * VP + nt * 8 + lq;
                mma1688(oacc[nt], a,
                        __float_as_uint(vp[0]), __float_as_uint(vp[4 * VP]));
            }
        }
        __syncthreads();
    }

    const float inv0 = 1.f / lrow0;
    const float inv1 = 1.f / lrow1;
    float* Og = g_attn + (size_t)(b * SS + qt * FBM + m0 + lq) * DM + qh * HD;
    #pragma unroll
    for (int nt = 0; nt < 16; nt++) {
        const int cb = nt * 8 + 2 * lr;
        *(float2*)(Og + cb) =
            make_float2(f2tf32f(oacc[nt][0] * inv0), f2tf32f(oacc[nt][1] * inv0));
        *(float2*)(Og + (size_t)8 * DM + cb) =
            make_float2(f2tf32f(oacc[nt][2] * inv1), f2tf32f(oacc[nt][3] * inv1));
    }
}

// ---------------------------------------------------------------------------
// Launch
// ---------------------------------------------------------------------------
extern "C" void kernel_launch(void* const* d_in, const int* in_sizes, int n_in,
                              void* d_out, int out_size)
{
    const float* hs   = (const float*)d_in[0];
    const float* cosb = (const float*)d_in[1];
    const float* sinb = (const float*)d_in[2];
    const float* Wqkv = (const float*)d_in[3];
    const float* Wout = (const float*)d_in[4];
    float* out = (float*)d_out;

    float *qkv_ptr, *attn_ptr, *rA, *rWq, *rWo;
    cudaGetSymbolAddress((void**)&qkv_ptr,  g_qkv);
    cudaGetSymbolAddress((void**)&attn_ptr, g_attn);
    cudaGetSymbolAddress((void**)&rA,  g_rA);
    cudaGetSymbolAddress((void**)&rWq, g_rWq);
    cudaGetSymbolAddress((void**)&rWo, g_rWo);

    cudaFuncSetAttribute(tf32gemm_k, cudaFuncAttributeMaxDynamicSharedMemorySize,
                         TF_SMEM_BYTES);
    cudaFuncSetAttribute(fattn_k, cudaFuncAttributeMaxDynamicSharedMemorySize,
                         FA_SMEM_BYTES);

    // 0) round activations; round+transpose weights to [N][K]
    round_k<<<592, 256>>>(hs, rA, (size_t)MROWS * DM / 4);
    tround_k<<<dim3(QKVD / 32, DM / 32), dim3(32, 8)>>>(Wqkv, rWq, DM, QKVD);
    tround_k<<<dim3(DM / 32, DM / 32),   dim3(32, 8)>>>(Wout, rWo, DM, DM);

    // 1) QKV projection
    tf32gemm_k<<<dim3(QKVD / TBN, MROWS / TBM), 256, TF_SMEM_BYTES>>>(
        rA, rWq, qkv_ptr, MROWS, QKVD, DM);

    // 2) RoPE + tf32 rounding of Q/K/V
    rope_k<<<MROWS, 256>>>(cosb, sinb);

    // 3) Causal GQA flash attention
    fattn_k<<<dim3(SS / FBM, NH, BB), 256, FA_SMEM_BYTES>>>();

    // 4) Output projection
    tf32gemm_k<<<dim3(DM / TBN, MROWS / TBM), 256, TF_SMEM_BYTES>>>(
        attn_ptr, rWo, out, MROWS, DM, DM);
}

// round 9
// speedup vs baseline: 7.3926x; 1.7787x over previous
#include <cuda_runtime.h>
#include <cuda_fp16.h>
#include <cstdint>
#include <math.h>

// Problem constants
#define BB      2
#define SS      2048
#define DM      4096
#define NH      32
#define NKV     8
#define HD      128
#define QKVD    6144          // (32 + 2*8) * 128
#define MROWS   4096          // B*S

// Scratch (allocation-free rule: __device__ globals)
__device__ float  g_qkv  [(size_t)MROWS * QKVD];   // fp32 qkv projection output
__device__ __half g_qkv16[(size_t)MROWS * QKVD];   // fp16 qkv after RoPE
__device__ __half g_attn [(size_t)MROWS * DM];     // fp16 attention output
__device__ __half g_rA   [(size_t)MROWS * DM];     // fp16 hidden_states
__device__ __half g_rWq  [(size_t)DM * QKVD];      // fp16 W_qkv, TRANSPOSED [N][K]
__device__ __half g_rWo  [(size_t)DM * DM];        // fp16 W_out,  TRANSPOSED [N][K]

__device__ __forceinline__ float ex2f(float x) {
    float r;
    asm("ex2.approx.f32 %0, %1;\n" : "=f"(r) : "f"(x));
    return r;
}
__device__ __forceinline__ void cp_async16(uint32_t smem, const void* gmem) {
    asm volatile("cp.async.cg.shared.global [%0], [%1], 16;\n" :: "r"(smem), "l"(gmem));
}
__device__ __forceinline__ void ldsm4(uint32_t* r, uint32_t addr) {
    asm volatile("ldmatrix.sync.aligned.m8n8.x4.shared.b16 {%0,%1,%2,%3}, [%4];"
                 : "=r"(r[0]), "=r"(r[1]), "=r"(r[2]), "=r"(r[3]) : "r"(addr));
}
__device__ __forceinline__ void ldsm4t(uint32_t* r, uint32_t addr) {
    asm volatile("ldmatrix.sync.aligned.m8n8.x4.trans.shared.b16 {%0,%1,%2,%3}, [%4];"
                 : "=r"(r[0]), "=r"(r[1]), "=r"(r[2]), "=r"(r[3]) : "r"(addr));
}
__device__ __forceinline__ void mma16816(float* d, const uint32_t* a,
                                         uint32_t b0, uint32_t b1) {
    asm volatile(
        "mma.sync.aligned.m16n8k16.row.col.f32.f16.f16.f32 "
        "{%0,%1,%2,%3}, {%4,%5,%6,%7}, {%8,%9}, {%0,%1,%2,%3};\n"
        : "+f"(d[0]), "+f"(d[1]), "+f"(d[2]), "+f"(d[3])
        : "r"(a[0]), "r"(a[1]), "r"(a[2]), "r"(a[3]), "r"(b0), "r"(b1));
}

// ---------------------------------------------------------------------------
// fp32 -> fp16 elementwise convert
// ---------------------------------------------------------------------------
__global__ void cvt_k(const float* __restrict__ in, __half* __restrict__ out, size_t n4)
{
    for (size_t i = (size_t)blockIdx.x * blockDim.x + threadIdx.x; i < n4;
         i += (size_t)gridDim.x * blockDim.x) {
        float4 v = ((const float4*)in)[i];
        __half2* o = (__half2*)out + 2 * i;
        o[0] = __floats2half2_rn(v.x, v.y);
        o[1] = __floats2half2_rn(v.z, v.w);
    }
}

// ---------------------------------------------------------------------------
// Tiled transpose + fp16 convert: in[K][N] fp32 row-major -> out[N][K] fp16
// ---------------------------------------------------------------------------
__global__ void tcvt_k(const float* __restrict__ in, __half* __restrict__ out,
                       int K, int N)
{
    __shared__ float t[32][33];
    const int k0 = blockIdx.y * 32, n0 = blockIdx.x * 32;
    const int x = threadIdx.x, y = threadIdx.y;   // block (32, 8)
    #pragma unroll
    for (int i = 0; i < 32; i += 8)
        t[y + i][x] = in[(size_t)(k0 + y + i) * N + n0 + x];
    __syncthreads();
    #pragma unroll
    for (int i = 0; i < 32; i += 8)
        out[(size_t)(n0 + y + i) * K + k0 + x] = __float2half_rn(t[x][y + i]);
}

// ---------------------------------------------------------------------------
// FP16 tensor-core GEMM: C[M,N] = A[M,K] @ Bt[N,K]^T (fp16 in, fp32 out).
// 128x128 tile, k-chunks of 32 halves, 3-stage cp.async, 2 CTAs/SM, LDSM.
// ---------------------------------------------------------------------------
#define HTBK 32                           // halves per k-tile
#define HPITCH 40                         // halves (80B rows, LDSM conflict-free)
#define HNSTAGE 3
#define HTILE (128 * HPITCH)              // halves per operand tile
#define HSTAGE (2 * HTILE)
#define HG_SMEM_BYTES (HNSTAGE * HSTAGE * 2)   // 61440 B -> 2 CTAs/SM

__global__ __launch_bounds__(256, 2) void hgemm_k(
    const __half* __restrict__ A, const __half* __restrict__ Bt,
    float* __restrict__ C, int M, int N, int K)
{
    extern __shared__ __align__(16) __half hsm[];
    const uint32_t tsu = (uint32_t)__cvta_generic_to_shared(hsm);

    const int tid  = threadIdx.x;
    const int lane = tid & 31;
    const int wid  = tid >> 5;
    const int wm   = wid >> 2;            // 0..1 -> 64 rows
    const int wn   = wid & 3;             // 0..3 -> 32 cols
    const int bm   = blockIdx.y * 128;
    const int bn   = blockIdx.x * 128;
    const int lq   = lane >> 2;
    const int lr   = lane & 3;

    const int q  = lane >> 3, rl = lane & 7;
    const int arow = (q & 1) * 8 + rl,  acol = (q >> 1) * 8;   // A-frag lane map
    const int brow = (q >> 1) * 8 + rl, bcol = (q & 1) * 8;    // B-frag lane map

    float acc[4][4][4];
    #pragma unroll
    for (int i = 0; i < 4; i++)
        #pragma unroll
        for (int j = 0; j < 4; j++)
            #pragma unroll
            for (int c = 0; c < 4; c++) acc[i][j][c] = 0.f;

    const int KT = K / HTBK;

    auto issue = [&](int kt, int buf) {
        const uint32_t sAu = tsu + (uint32_t)(buf * HSTAGE) * 2;
        const uint32_t sBu = sAu + (uint32_t)HTILE * 2;
        const __half* Ag = A  + (size_t)bm * K + kt * HTBK;
        const __half* Bg = Bt + (size_t)bn * K + kt * HTBK;
        #pragma unroll
        for (int qq = 0; qq < 2; qq++) {
            const int i = qq * 256 + tid;
            const int row = i >> 2, c8 = (i & 3) * 8;
            cp_async16(sAu + (uint32_t)(row * HPITCH + c8) * 2,
                       Ag + (size_t)row * K + c8);
            cp_async16(sBu + (uint32_t)(row * HPITCH + c8) * 2,
                       Bg + (size_t)row * K + c8);
        }
        asm volatile("cp.async.commit_group;\n");
    };

    issue(0, 0);
    issue(1, 1);

    for (int kt = 0; kt < KT; kt++) {
        asm volatile("cp.async.wait_group 1;\n");
        __syncthreads();

        const int nk = kt + 2;
        if (nk < KT) issue(nk, nk % HNSTAGE);
        else         asm volatile("cp.async.commit_group;\n");

        const uint32_t sAu = tsu + (uint32_t)((kt % HNSTAGE) * HSTAGE) * 2;
        const uint32_t sBu = sAu + (uint32_t)HTILE * 2;

        #pragma unroll
        for (int ks = 0; ks < 2; ks++) {
            const int k0 = ks * 16;
            uint32_t af[4][4], bf[2][4];
            #pragma unroll
            for (int mt = 0; mt < 4; mt++)
                ldsm4(af[mt], sAu + (uint32_t)((wm * 64 + mt * 16 + arow) * HPITCH
                                               + k0 + acol) * 2);
            #pragma unroll
            for (int p = 0; p < 2; p++)
                ldsm4(bf[p], sBu + (uint32_t)((wn * 32 + p * 16 + brow) * HPITCH
                                              + k0 + bcol) * 2);
            #pragma unroll
            for (int mt = 0; mt < 4; mt++)
                #pragma unroll
                for (int p = 0; p < 2; p++) {
                    mma16816(acc[mt][2 * p],     af[mt], bf[p][0], bf[p][1]);
                    mma16816(acc[mt][2 * p + 1], af[mt], bf[p][2], bf[p][3]);
                }
        }
        // no trailing syncthreads: with 3 stages the next iteration's top
        // barrier orders this iteration's readers before the stage is rewritten
    }

    #pragma unroll
    for (int mt = 0; mt < 4; mt++) {
        #pragma unroll
        for (int nt = 0; nt < 4; nt++) {
            const int row = bm + wm * 64 + mt * 16 + lq;
            const int col = bn + wn * 32 + nt * 8 + 2 * lr;
            float* c0 = C + (size_t)row * N + col;
            float* c1 = C + (size_t)(row + 8) * N + col;
            *(float2*)c0 = make_float2(acc[mt][nt][0], acc[mt][nt][1]);
            *(float2*)c1 = make_float2(acc[mt][nt][2], acc[mt][nt][3]);
        }
    }
}

// ---------------------------------------------------------------------------
// RoPE on Q/K + fp16 convert of Q, K, V: g_qkv (fp32) -> g_qkv16 (fp16)
// ---------------------------------------------------------------------------
__global__ void rope16_k(const float* __restrict__ cost, const float* __restrict__ sint)
{
    const int row = blockIdx.x;            // 0..4095
    const int s   = row & (SS - 1);
    const float* qf = g_qkv   + (size_t)row * QKVD;
    __half*      qo = g_qkv16 + (size_t)row * QKVD;

    const int NROPE = (NH + NKV) * 64;
    const int NV    = NKV * HD;
    for (int p = threadIdx.x; p < NROPE + NV; p += blockDim.x) {
        if (p < NROPE) {
            const int h = p >> 6;
            const int d = p & 63;
            const int base = h * HD;
            const float c  = cost[s * HD + d];
            const float sn = sint[s * HD + d];
            const float x1 = qf[base + d];
            const float x2 = qf[base + d + 64];
            qo[base + d]      = __float2half_rn(x1 * c - x2 * sn);
            qo[base + d + 64] = __float2half_rn(x2 * c + x1 * sn);
        } else {
            const int idx = (NH + NKV) * HD + (p - NROPE);
            qo[idx] = __float2half_rn(qf[idx]);
        }
    }
}

// ---------------------------------------------------------------------------
// Flash attention, fp16 mma.sync, cp.async pipelined K/V, LDSM everywhere.
// Q[128][136h] K 2x[64][136h] V[64][136h] P[128][72h] -> 105472 B, 2 CTAs/SM
// ---------------------------------------------------------------------------
#define QPH 136
#define KPH 136
#define VPH 136
#define SPH 72
#define FA_QO  0
#define FA_K0  (128 * QPH)
#define FA_K1  (FA_K0 + 64 * KPH)
#define FA_VO  (FA_K1 + 64 * KPH)
#define FA_PO  (FA_VO + 64 * VPH)
#define FA_SMEM_HALVES (FA_PO + 128 * SPH)
#define FA_SMEM_BYTES  (FA_SMEM_HALVES * 2)   // 105472 B

__global__ __launch_bounds__(256, 2) void fattn_k()
{
    extern __shared__ __align__(16) __half fsm[];
    __half* Qs = fsm + FA_QO;
    __half* Ps = fsm + FA_PO;
    const uint32_t bsu = (uint32_t)__cvta_generic_to_shared(fsm);
    const uint32_t qsu = bsu + FA_QO * 2;
    const uint32_t k0u = bsu + FA_K0 * 2;
    const uint32_t k1u = bsu + FA_K1 * 2;
    const uint32_t vsu = bsu + FA_VO * 2;
    const uint32_t psu = bsu + FA_PO * 2;

    const int qt  = blockIdx.x;           // 0..15
    const int qh  = blockIdx.y;
    const int b   = blockIdx.z;
    const int kh  = qh >> 2;
    const int tid = threadIdx.x;
    const int lane = tid & 31;
    const int w   = tid >> 5;
    const int lq  = lane >> 2;
    const int lr  = lane & 3;
    const int m0  = w * 16;

    const int q  = lane >> 3, rl = lane & 7;
    const int arow = (q & 1) * 8 + rl,  acol = (q >> 1) * 8;
    const int brow = (q >> 1) * 8 + rl, bcol = (q & 1) * 8;

    const __half* Qg = g_qkv16 + (size_t)(b * SS + qt * 128) * QKVD + qh * HD;
    const __half* Kg = g_qkv16 + (size_t)(b * SS) * QKVD + NH * HD + kh * HD;
    const __half* Vg = g_qkv16 + (size_t)(b * SS) * QKVD + (NH + NKV) * HD + kh * HD;

    const float scale2 = 0.08838834764831845f * 1.4426950408889634f;

    auto cpK = [&](int kt2, uint32_t dst) {
        #pragma unroll
        for (int qq = 0; qq < 4; qq++) {
            const int i = qq * 256 + tid;          // 1024 chunks of 16B
            const int r = i >> 4, c8 = (i & 15) * 8;
            cp_async16(dst + (uint32_t)(r * KPH + c8) * 2,
                       Kg + (size_t)(kt2 * 64 + r) * QKVD + c8);
        }
        asm volatile("cp.async.commit_group;\n");
    };
    auto cpV = [&](int kt2) {
        #pragma unroll
        for (int qq = 0; qq < 4; qq++) {
            const int i = qq * 256 + tid;
            const int r = i >> 4, c8 = (i & 15) * 8;
            cp_async16(vsu + (uint32_t)(r * VPH + c8) * 2,
                       Vg + (size_t)(kt2 * 64 + r) * QKVD + c8);
        }
        asm volatile("cp.async.commit_group;\n");
    };

    // Q load (plain vectorized) + prefetch K tile 0
    for (int i = tid; i < 128 * 16; i += 256) {
        const int r = i >> 4, c8 = (i & 15) * 8;
        *(uint4*)&Qs[r * QPH + c8] = *(const uint4*)(Qg + (size_t)r * QKVD + c8);
    }
    cpK(0, k0u);

    float oacc[16][4];
    #pragma unroll
    for (int i = 0; i < 16; i++)
        #pragma unroll
        for (int c = 0; c < 4; c++) oacc[i][c] = 0.f;
    float mrow0 = -1e30f, mrow1 = -1e30f;
    float lrow0 = 0.f,    lrow1 = 0.f;

    const int ktmax = 2 * qt + 2;
    for (int kt2 = 0; kt2 < ktmax; kt2++) {
        cpV(kt2);
        asm volatile("cp.async.wait_group 1;\n");    // K_cur complete
        __syncthreads();

        const uint32_t kcu = (kt2 & 1) ? k1u : k0u;

        // S = Q K^T
        float sacc[8][4];
        #pragma unroll
        for (int i = 0; i < 8; i++)
            #pragma unroll
            for (int c = 0; c < 4; c++) sacc[i][c] = 0.f;

        #pragma unroll
        for (int k = 0; k < 8; k++) {
            const int k0 = k * 16;
            uint32_t a[4], bf[4];
            ldsm4(a, qsu + (uint32_t)((m0 + arow) * QPH + k0 + acol) * 2);
            #pragma unroll
            for (int np = 0; np < 4; np++) {
                ldsm4(bf, kcu + (uint32_t)((np * 16 + brow) * KPH + k0 + bcol) * 2);
                mma16816(sacc[2 * np],     a, bf[0], bf[1]);
                mma16816(sacc[2 * np + 1], a, bf[2], bf[3]);
            }
        }

        const bool need_mask = (kt2 >= 2 * qt);
        const int r0 = qt * 128 + m0 + lq;
        const int r1 = r0 + 8;
        #pragma unroll
        for (int nt = 0; nt < 8; nt++) {
            const int colb = kt2 * 64 + nt * 8 + 2 * lr;
            #pragma unroll
            for (int c = 0; c < 4; c++) sacc[nt][c] *= scale2;
            if (need_mask) {
                if (colb     > r0) sacc[nt][0] = -1e30f;
                if (colb + 1 > r0) sacc[nt][1] = -1e30f;
                if (colb     > r1) sacc[nt][2] = -1e30f;
                if (colb + 1 > r1) sacc[nt][3] = -1e30f;
            }
        }

        // Online softmax (base-2 domain)
        float mx0 = -1e30f, mx1 = -1e30f;
        #pragma unroll
        for (int nt = 0; nt < 8; nt++) {
            mx0 = fmaxf(mx0, fmaxf(sacc[nt][0], sacc[nt][1]));
            mx1 = fmaxf(mx1, fmaxf(sacc[nt][2], sacc[nt][3]));
        }
        mx0 = fmaxf(mx0, __shfl_xor_sync(0xffffffffu, mx0, 1));
        mx0 = fmaxf(mx0, __shfl_xor_sync(0xffffffffu, mx0, 2));
        mx1 = fmaxf(mx1, __shfl_xor_sync(0xffffffffu, mx1, 1));
        mx1 = fmaxf(mx1, __shfl_xor_sync(0xffffffffu, mx1, 2));

        const float mn0 = fmaxf(mrow0, mx0);
        const float mn1 = fmaxf(mrow1, mx1);
        const float scl0 = ex2f(mrow0 - mn0);
        const float scl1 = ex2f(mrow1 - mn1);
        mrow0 = mn0; mrow1 = mn1;

        float rs0 = 0.f, rs1 = 0.f;
        #pragma unroll
        for (int nt = 0; nt < 8; nt++) {
            const float p0 = ex2f(sacc[nt][0] - mn0);
            const float p1 = ex2f(sacc[nt][1] - mn0);
            const float p2 = ex2f(sacc[nt][2] - mn1);
            const float p3 = ex2f(sacc[nt][3] - mn1);
            rs0 += p0 + p1;
            rs1 += p2 + p3;
            const int cb = nt * 8 + 2 * lr;
            *(__half2*)&Ps[(m0 + lq) * SPH + cb]     = __floats2half2_rn(p0, p1);
            *(__half2*)&Ps[(m0 + lq + 8) * SPH + cb] = __floats2half2_rn(p2, p3);
        }
        rs0 += __shfl_xor_sync(0xffffffffu, rs0, 1);
        rs0 += __shfl_xor_sync(0xffffffffu, rs0, 2);
        rs1 += __shfl_xor_sync(0xffffffffu, rs1, 1);
        rs1 += __shfl_xor_sync(0xffffffffu, rs1, 2);
        lrow0 = lrow0 * scl0 + rs0;
        lrow1 = lrow1 * scl1 + rs1;

        #pragma unroll
        for (int nt = 0; nt < 16; nt++) {
            oacc[nt][0] *= scl0; oacc[nt][1] *= scl0;
            oacc[nt][2] *= scl1; oacc[nt][3] *= scl1;
        }
        __syncwarp();   // this warp's P rows complete before LDSM reads

        if (kt2 + 1 < ktmax) cpK(kt2 + 1, ((kt2 + 1) & 1) ? k1u : k0u);
        else asm volatile("cp.async.commit_group;\n");

        asm volatile("cp.async.wait_group 1;\n");    // V_cur complete
        __syncthreads();

        // O += P V  (P via LDSM, V via LDSM.trans)
        #pragma unroll
        for (int k = 0; k < 4; k++) {
            const int k0 = k * 16;
            uint32_t a[4];
            ldsm4(a, psu + (uint32_t)((m0 + arow) * SPH + k0 + acol) * 2);
            #pragma unroll
            for (int np = 0; np < 8; np++) {
                uint32_t bf[4];
                ldsm4t(bf, vsu + (uint32_t)((k0 + arow) * VPH + np * 16 + acol) * 2);
                mma16816(oacc[2 * np],     a, bf[0], bf[1]);
                mma16816(oacc[2 * np + 1], a, bf[2], bf[3]);
            }
        }
        __syncthreads();   // protect Vs before next iteration's cpV
    }

    const float inv0 = 1.f / lrow0;
    const float inv1 = 1.f / lrow1;
    __half* Og = g_attn + (size_t)(b * SS + qt * 128 + m0 + lq) * DM + qh * HD;
    #pragma unroll
    for (int nt = 0; nt < 16; nt++) {
        const int cb = nt * 8 + 2 * lr;
        *(__half2*)(Og + cb) =
            __floats2half2_rn(oacc[nt][0] * inv0, oacc[nt][1] * inv0);
        *(__half2*)(Og + (size_t)8 * DM + cb) =
            __floats2half2_rn(oacc[nt][2] * inv1, oacc[nt][3] * inv1);
    }
}

// ---------------------------------------------------------------------------
// Launch
// ---------------------------------------------------------------------------
extern "C" void kernel_launch(void* const* d_in, const int* in_sizes, int n_in,
                              void* d_out, int out_size)
{
    const float* hs   = (const float*)d_in[0];
    const float* cosb = (const float*)d_in[1];
    const float* sinb = (const float*)d_in[2];
    const float* Wqkv = (const float*)d_in[3];
    const float* Wout = (const float*)d_in[4];
    float* out = (float*)d_out;

    float*  qkv_ptr;
    __half *attn_ptr, *rA, *rWq, *rWo;
    cudaGetSymbolAddress((void**)&qkv_ptr,  g_qkv);
    cudaGetSymbolAddress((void**)&attn_ptr, g_attn);
    cudaGetSymbolAddress((void**)&rA,  g_rA);
    cudaGetSymbolAddress((void**)&rWq, g_rWq);
    cudaGetSymbolAddress((void**)&rWo, g_rWo);

    cudaFuncSetAttribute(hgemm_k, cudaFuncAttributeMaxDynamicSharedMemorySize,
                         HG_SMEM_BYTES);
    cudaFuncSetAttribute(fattn_k, cudaFuncAttributeMaxDynamicSharedMemorySize,
                         FA_SMEM_BYTES);

    // 0) fp16 conversion of activations; transpose+convert of weights
    cvt_k<<<592, 256>>>(hs, rA, (size_t)MROWS * DM / 4);
    tcvt_k<<<dim3(QKVD / 32, DM / 32), dim3(32, 8)>>>(Wqkv, rWq, DM, QKVD);
    tcvt_k<<<dim3(DM / 32, DM / 32),   dim3(32, 8)>>>(Wout, rWo, DM, DM);

    // 1) QKV projection (fp16 MMA, fp32 accum/out)
    hgemm_k<<<dim3(QKVD / 128, MROWS / 128), 256, HG_SMEM_BYTES>>>(
        rA, rWq, qkv_ptr, MROWS, QKVD, DM);

    // 2) RoPE + fp16 convert of Q/K/V
    rope16_k<<<MROWS, 256>>>(cosb, sinb);

    // 3) Causal GQA flash attention (fp16)
    fattn_k<<<dim3(SS / 128, NH, BB), 256, FA_SMEM_BYTES>>>();

    // 4) Output projection (fp16 MMA, fp32 out)
    hgemm_k<<<dim3(DM / 128, MROWS / 128), 256, HG_SMEM_BYTES>>>(
        attn_ptr, rWo, out, MROWS, DM, DM);
}

// round 10
// speedup vs baseline: 7.9317x; 1.0729x over previous
#include <cuda_runtime.h>
#include <cuda_fp16.h>
#include <cstdint>
#include <math.h>

// Problem constants
#define BB      2
#define SS      2048
#define DM      4096
#define NH      32
#define NKV     8
#define HD      128
#define QKVD    6144          // (32 + 2*8) * 128
#define MROWS   4096          // B*S

// Scratch (allocation-free rule: __device__ globals)
__device__ float  g_qkv  [(size_t)MROWS * QKVD];   // fp32 qkv projection output
__device__ __half g_qkv16[(size_t)MROWS * QKVD];   // fp16 qkv after RoPE
__device__ __half g_attn [(size_t)MROWS * DM];     // fp16 attention output
__device__ __half g_rA   [(size_t)MROWS * DM];     // fp16 hidden_states
__device__ __half g_rWq  [(size_t)DM * QKVD];      // fp16 W_qkv, TRANSPOSED [N][K]
__device__ __half g_rWo  [(size_t)DM * DM];        // fp16 W_out,  TRANSPOSED [N][K]

__device__ __forceinline__ float ex2f(float x) {
    float r;
    asm("ex2.approx.f32 %0, %1;\n" : "=f"(r) : "f"(x));
    return r;
}
__device__ __forceinline__ void cp_async16(uint32_t smem, const void* gmem) {
    asm volatile("cp.async.cg.shared.global [%0], [%1], 16;\n" :: "r"(smem), "l"(gmem));
}
__device__ __forceinline__ void ldsm4(uint32_t* r, uint32_t addr) {
    asm volatile("ldmatrix.sync.aligned.m8n8.x4.shared.b16 {%0,%1,%2,%3}, [%4];"
                 : "=r"(r[0]), "=r"(r[1]), "=r"(r[2]), "=r"(r[3]) : "r"(addr));
}
__device__ __forceinline__ void ldsm4t(uint32_t* r, uint32_t addr) {
    asm volatile("ldmatrix.sync.aligned.m8n8.x4.trans.shared.b16 {%0,%1,%2,%3}, [%4];"
                 : "=r"(r[0]), "=r"(r[1]), "=r"(r[2]), "=r"(r[3]) : "r"(addr));
}
__device__ __forceinline__ void mma16816(float* d, const uint32_t* a,
                                         uint32_t b0, uint32_t b1) {
    asm volatile(
        "mma.sync.aligned.m16n8k16.row.col.f32.f16.f16.f32 "
        "{%0,%1,%2,%3}, {%4,%5,%6,%7}, {%8,%9}, {%0,%1,%2,%3};\n"
        : "+f"(d[0]), "+f"(d[1]), "+f"(d[2]), "+f"(d[3])
        : "r"(a[0]), "r"(a[1]), "r"(a[2]), "r"(a[3]), "r"(b0), "r"(b1));
}

// ---------------------------------------------------------------------------
// fp32 -> fp16 elementwise convert
// ---------------------------------------------------------------------------
__global__ void cvt_k(const float* __restrict__ in, __half* __restrict__ out, size_t n4)
{
    for (size_t i = (size_t)blockIdx.x * blockDim.x + threadIdx.x; i < n4;
         i += (size_t)gridDim.x * blockDim.x) {
        float4 v = ((const float4*)in)[i];
        __half2* o = (__half2*)out + 2 * i;
        o[0] = __floats2half2_rn(v.x, v.y);
        o[1] = __floats2half2_rn(v.z, v.w);
    }
}

// ---------------------------------------------------------------------------
// Tiled transpose + fp16 convert: in[K][N] fp32 row-major -> out[N][K] fp16
// ---------------------------------------------------------------------------
__global__ void tcvt_k(const float* __restrict__ in, __half* __restrict__ out,
                       int K, int N)
{
    __shared__ float t[32][33];
    const int k0 = blockIdx.y * 32, n0 = blockIdx.x * 32;
    const int x = threadIdx.x, y = threadIdx.y;   // block (32, 8)
    #pragma unroll
    for (int i = 0; i < 32; i += 8)
        t[y + i][x] = in[(size_t)(k0 + y + i) * N + n0 + x];
    __syncthreads();
    #pragma unroll
    for (int i = 0; i < 32; i += 8)
        out[(size_t)(n0 + y + i) * K + k0 + x] = __float2half_rn(t[x][y + i]);
}

// ---------------------------------------------------------------------------
// FP16 tensor-core GEMM: C[M,N] = A[M,K] @ Bt[N,K]^T (fp16 in, fp32 out).
// 128x128 tile, k-chunks of 64 halves, 3-stage cp.async, 2 CTAs/SM, LDSM.
// ---------------------------------------------------------------------------
#define HTBK 64                           // halves per k-tile
#define HPITCH 72                         // halves (144B rows, LDSM conflict-free)
#define HNSTAGE 3
#define HTILE (128 * HPITCH)              // halves per operand tile
#define HSTAGE (2 * HTILE)
#define HG_SMEM_BYTES (HNSTAGE * HSTAGE * 2)   // 110592 B -> 2 CTAs/SM (216KB)

__global__ __launch_bounds__(256, 2) void hgemm_k(
    const __half* __restrict__ A, const __half* __restrict__ Bt,
    float* __restrict__ C, int M, int N, int K)
{
    extern __shared__ __align__(16) __half hsm[];
    const uint32_t tsu = (uint32_t)__cvta_generic_to_shared(hsm);

    const int tid  = threadIdx.x;
    const int lane = tid & 31;
    const int wid  = tid >> 5;
    const int wm   = wid >> 2;            // 0..1 -> 64 rows
    const int wn   = wid & 3;             // 0..3 -> 32 cols
    const int bm   = blockIdx.y * 128;
    const int bn   = blockIdx.x * 128;
    const int lq   = lane >> 2;
    const int lr   = lane & 3;

    const int q  = lane >> 3, rl = lane & 7;
    const int arow = (q & 1) * 8 + rl,  acol = (q >> 1) * 8;   // A-frag lane map
    const int brow = (q >> 1) * 8 + rl, bcol = (q & 1) * 8;    // B-frag lane map

    float acc[4][4][4];
    #pragma unroll
    for (int i = 0; i < 4; i++)
        #pragma unroll
        for (int j = 0; j < 4; j++)
            #pragma unroll
            for (int c = 0; c < 4; c++) acc[i][j][c] = 0.f;

    const int KT = K / HTBK;

    auto issue = [&](int kt, int buf) {
        const uint32_t sAu = tsu + (uint32_t)(buf * HSTAGE) * 2;
        const uint32_t sBu = sAu + (uint32_t)HTILE * 2;
        const __half* Ag = A  + (size_t)bm * K + kt * HTBK;
        const __half* Bg = Bt + (size_t)bn * K + kt * HTBK;
        #pragma unroll
        for (int qq = 0; qq < 4; qq++) {
            const int i = qq * 256 + tid;          // 1024 chunks of 16B per tile
            const int row = i >> 3, c8 = (i & 7) * 8;
            cp_async16(sAu + (uint32_t)(row * HPITCH + c8) * 2,
                       Ag + (size_t)row * K + c8);
            cp_async16(sBu + (uint32_t)(row * HPITCH + c8) * 2,
                       Bg + (size_t)row * K + c8);
        }
        asm volatile("cp.async.commit_group;\n");
    };

    issue(0, 0);
    issue(1, 1);

    for (int kt = 0; kt < KT; kt++) {
        asm volatile("cp.async.wait_group 1;\n");
        __syncthreads();

        const int nk = kt + 2;
        if (nk < KT) issue(nk, nk % HNSTAGE);
        else         asm volatile("cp.async.commit_group;\n");

        const uint32_t sAu = tsu + (uint32_t)((kt % HNSTAGE) * HSTAGE) * 2;
        const uint32_t sBu = sAu + (uint32_t)HTILE * 2;

        #pragma unroll
        for (int ks = 0; ks < 4; ks++) {
            const int k0 = ks * 16;
            uint32_t af[4][4], bf[2][4];
            #pragma unroll
            for (int mt = 0; mt < 4; mt++)
                ldsm4(af[mt], sAu + (uint32_t)((wm * 64 + mt * 16 + arow) * HPITCH
                                               + k0 + acol) * 2);
            #pragma unroll
            for (int p = 0; p < 2; p++)
                ldsm4(bf[p], sBu + (uint32_t)((wn * 32 + p * 16 + brow) * HPITCH
                                              + k0 + bcol) * 2);
            #pragma unroll
            for (int mt = 0; mt < 4; mt++)
                #pragma unroll
                for (int p = 0; p < 2; p++) {
                    mma16816(acc[mt][2 * p],     af[mt], bf[p][0], bf[p][1]);
                    mma16816(acc[mt][2 * p + 1], af[mt], bf[p][2], bf[p][3]);
                }
        }
        // no trailing syncthreads: with 3 stages the next iteration's top
        // barrier orders this iteration's readers before the stage is rewritten
    }

    #pragma unroll
    for (int mt = 0; mt < 4; mt++) {
        #pragma unroll
        for (int nt = 0; nt < 4; nt++) {
            const int row = bm + wm * 64 + mt * 16 + lq;
            const int col = bn + wn * 32 + nt * 8 + 2 * lr;
            float* c0 = C + (size_t)row * N + col;
            float* c1 = C + (size_t)(row + 8) * N + col;
            *(float2*)c0 = make_float2(acc[mt][nt][0], acc[mt][nt][1]);
            *(float2*)c1 = make_float2(acc[mt][nt][2], acc[mt][nt][3]);
        }
    }
}

// ---------------------------------------------------------------------------
// RoPE on Q/K + fp16 convert of Q, K, V: g_qkv (fp32) -> g_qkv16 (fp16)
// ---------------------------------------------------------------------------
__global__ void rope16_k(const float* __restrict__ cost, const float* __restrict__ sint)
{
    const int row = blockIdx.x;            // 0..4095
    const int s   = row & (SS - 1);
    const float* qf = g_qkv   + (size_t)row * QKVD;
    __half*      qo = g_qkv16 + (size_t)row * QKVD;

    const int NROPE = (NH + NKV) * 64;
    const int NV    = NKV * HD;
    for (int p = threadIdx.x; p < NROPE + NV; p += blockDim.x) {
        if (p < NROPE) {
            const int h = p >> 6;
            const int d = p & 63;
            const int base = h * HD;
            const float c  = cost[s * HD + d];
            const float sn = sint[s * HD + d];
            const float x1 = qf[base + d];
            const float x2 = qf[base + d + 64];
            qo[base + d]      = __float2half_rn(x1 * c - x2 * sn);
            qo[base + d + 64] = __float2half_rn(x2 * c + x1 * sn);
        } else {
            const int idx = (NH + NKV) * HD + (p - NROPE);
            qo[idx] = __float2half_rn(qf[idx]);
        }
    }
}

// ---------------------------------------------------------------------------
// Flash attention, fp16 mma.sync, cp.async pipelined K/V, LDSM everywhere.
// Q[128][136h] K 2x[64][136h] V[64][136h] P[128][72h] -> 105472 B, 2 CTAs/SM
// ---------------------------------------------------------------------------
#define QPH 136
#define KPH 136
#define VPH 136
#define SPH 72
#define FA_QO  0
#define FA_K0  (128 * QPH)
#define FA_K1  (FA_K0 + 64 * KPH)
#define FA_VO  (FA_K1 + 64 * KPH)
#define FA_PO  (FA_VO + 64 * VPH)
#define FA_SMEM_HALVES (FA_PO + 128 * SPH)
#define FA_SMEM_BYTES  (FA_SMEM_HALVES * 2)   // 105472 B

__global__ __launch_bounds__(256, 2) void fattn_k()
{
    extern __shared__ __align__(16) __half fsm[];
    __half* Qs = fsm + FA_QO;
    __half* Ps = fsm + FA_PO;
    const uint32_t bsu = (uint32_t)__cvta_generic_to_shared(fsm);
    const uint32_t qsu = bsu + FA_QO * 2;
    const uint32_t k0u = bsu + FA_K0 * 2;
    const uint32_t k1u = bsu + FA_K1 * 2;
    const uint32_t vsu = bsu + FA_VO * 2;
    const uint32_t psu = bsu + FA_PO * 2;

    const int qt  = blockIdx.x;           // 0..15
    const int qh  = blockIdx.y;
    const int b   = blockIdx.z;
    const int kh  = qh >> 2;
    const int tid = threadIdx.x;
    const int lane = tid & 31;
    const int w   = tid >> 5;
    const int lq  = lane >> 2;
    const int lr  = lane & 3;
    const int m0  = w * 16;

    const int q  = lane >> 3, rl = lane & 7;
    const int arow = (q & 1) * 8 + rl,  acol = (q >> 1) * 8;
    const int brow = (q >> 1) * 8 + rl, bcol = (q & 1) * 8;

    const __half* Qg = g_qkv16 + (size_t)(b * SS + qt * 128) * QKVD + qh * HD;
    const __half* Kg = g_qkv16 + (size_t)(b * SS) * QKVD + NH * HD + kh * HD;
    const __half* Vg = g_qkv16 + (size_t)(b * SS) * QKVD + (NH + NKV) * HD + kh * HD;

    const float scale2 = 0.08838834764831845f * 1.4426950408889634f;

    auto cpK = [&](int kt2, uint32_t dst) {
        #pragma unroll
        for (int qq = 0; qq < 4; qq++) {
            const int i = qq * 256 + tid;          // 1024 chunks of 16B
            const int r = i >> 4, c8 = (i & 15) * 8;
            cp_async16(dst + (uint32_t)(r * KPH + c8) * 2,
                       Kg + (size_t)(kt2 * 64 + r) * QKVD + c8);
        }
        asm volatile("cp.async.commit_group;\n");
    };
    auto cpV = [&](int kt2) {
        #pragma unroll
        for (int qq = 0; qq < 4; qq++) {
            const int i = qq * 256 + tid;
            const int r = i >> 4, c8 = (i & 15) * 8;
            cp_async16(vsu + (uint32_t)(r * VPH + c8) * 2,
                       Vg + (size_t)(kt2 * 64 + r) * QKVD + c8);
        }
        asm volatile("cp.async.commit_group;\n");
    };

    // Q load (plain vectorized) + prefetch K tile 0
    for (int i = tid; i < 128 * 16; i += 256) {
        const int r = i >> 4, c8 = (i & 15) * 8;
        *(uint4*)&Qs[r * QPH + c8] = *(const uint4*)(Qg + (size_t)r * QKVD + c8);
    }
    cpK(0, k0u);

    float oacc[16][4];
    #pragma unroll
    for (int i = 0; i < 16; i++)
        #pragma unroll
        for (int c = 0; c < 4; c++) oacc[i][c] = 0.f;
    float mrow0 = -1e30f, mrow1 = -1e30f;
    float lrow0 = 0.f,    lrow1 = 0.f;

    const int ktmax = 2 * qt + 2;
    for (int kt2 = 0; kt2 < ktmax; kt2++) {
        cpV(kt2);
        asm volatile("cp.async.wait_group 1;\n");    // K_cur complete
        __syncthreads();

        const uint32_t kcu = (kt2 & 1) ? k1u : k0u;

        // S = Q K^T
        float sacc[8][4];
        #pragma unroll
        for (int i = 0; i < 8; i++)
            #pragma unroll
            for (int c = 0; c < 4; c++) sacc[i][c] = 0.f;

        #pragma unroll
        for (int k = 0; k < 8; k++) {
            const int k0 = k * 16;
            uint32_t a[4], bf[4];
            ldsm4(a, qsu + (uint32_t)((m0 + arow) * QPH + k0 + acol) * 2);
            #pragma unroll
            for (int np = 0; np < 4; np++) {
                ldsm4(bf, kcu + (uint32_t)((np * 16 + brow) * KPH + k0 + bcol) * 2);
                mma16816(sacc[2 * np],     a, bf[0], bf[1]);
                mma16816(sacc[2 * np + 1], a, bf[2], bf[3]);
            }
        }

        const bool need_mask = (kt2 >= 2 * qt);
        const int r0 = qt * 128 + m0 + lq;
        const int r1 = r0 + 8;
        #pragma unroll
        for (int nt = 0; nt < 8; nt++) {
            const int colb = kt2 * 64 + nt * 8 + 2 * lr;
            #pragma unroll
            for (int c = 0; c < 4; c++) sacc[nt][c] *= scale2;
            if (need_mask) {
                if (colb     > r0) sacc[nt][0] = -1e30f;
                if (colb + 1 > r0) sacc[nt][1] = -1e30f;
                if (colb     > r1) sacc[nt][2] = -1e30f;
                if (colb + 1 > r1) sacc[nt][3] = -1e30f;
            }
        }

        // Online softmax (base-2 domain)
        float mx0 = -1e30f, mx1 = -1e30f;
        #pragma unroll
        for (int nt = 0; nt < 8; nt++) {
            mx0 = fmaxf(mx0, fmaxf(sacc[nt][0], sacc[nt][1]));
            mx1 = fmaxf(mx1, fmaxf(sacc[nt][2], sacc[nt][3]));
        }
        mx0 = fmaxf(mx0, __shfl_xor_sync(0xffffffffu, mx0, 1));
        mx0 = fmaxf(mx0, __shfl_xor_sync(0xffffffffu, mx0, 2));
        mx1 = fmaxf(mx1, __shfl_xor_sync(0xffffffffu, mx1, 1));
        mx1 = fmaxf(mx1, __shfl_xor_sync(0xffffffffu, mx1, 2));

        const float mn0 = fmaxf(mrow0, mx0);
        const float mn1 = fmaxf(mrow1, mx1);
        const float scl0 = ex2f(mrow0 - mn0);
        const float scl1 = ex2f(mrow1 - mn1);
        mrow0 = mn0; mrow1 = mn1;

        float rs0 = 0.f, rs1 = 0.f;
        #pragma unroll
        for (int nt = 0; nt < 8; nt++) {
            const float p0 = ex2f(sacc[nt][0] - mn0);
            const float p1 = ex2f(sacc[nt][1] - mn0);
            const float p2 = ex2f(sacc[nt][2] - mn1);
            const float p3 = ex2f(sacc[nt][3] - mn1);
            rs0 += p0 + p1;
            rs1 += p2 + p3;
            const int cb = nt * 8 + 2 * lr;
            *(__half2*)&Ps[(m0 + lq) * SPH + cb]     = __floats2half2_rn(p0, p1);
            *(__half2*)&Ps[(m0 + lq + 8) * SPH + cb] = __floats2half2_rn(p2, p3);
        }
        rs0 += __shfl_xor_sync(0xffffffffu, rs0, 1);
        rs0 += __shfl_xor_sync(0xffffffffu, rs0, 2);
        rs1 += __shfl_xor_sync(0xffffffffu, rs1, 1);
        rs1 += __shfl_xor_sync(0xffffffffu, rs1, 2);
        lrow0 = lrow0 * scl0 + rs0;
        lrow1 = lrow1 * scl1 + rs1;

        #pragma unroll
        for (int nt = 0; nt < 16; nt++) {
            oacc[nt][0] *= scl0; oacc[nt][1] *= scl0;
            oacc[nt][2] *= scl1; oacc[nt][3] *= scl1;
        }
        __syncwarp();   // this warp's P rows complete before LDSM reads

        if (kt2 + 1 < ktmax) cpK(kt2 + 1, ((kt2 + 1) & 1) ? k1u : k0u);
        else asm volatile("cp.async.commit_group;\n");

        asm volatile("cp.async.wait_group 1;\n");    // V_cur complete
        __syncthreads();

        // O += P V  (P via LDSM, V via LDSM.trans)
        #pragma unroll
        for (int k = 0; k < 4; k++) {
            const int k0 = k * 16;
            uint32_t a[4];
            ldsm4(a, psu + (uint32_t)((m0 + arow) * SPH + k0 + acol) * 2);
            #pragma unroll
            for (int np = 0; np < 8; np++) {
                uint32_t bf[4];
                ldsm4t(bf, vsu + (uint32_t)((k0 + arow) * VPH + np * 16 + acol) * 2);
                mma16816(oacc[2 * np],     a, bf[0], bf[1]);
                mma16816(oacc[2 * np + 1], a, bf[2], bf[3]);
            }
        }
        __syncthreads();   // protect Vs before next iteration's cpV
    }

    const float inv0 = 1.f / lrow0;
    const float inv1 = 1.f / lrow1;
    __half* Og = g_attn + (size_t)(b * SS + qt * 128 + m0 + lq) * DM + qh * HD;
    #pragma unroll
    for (int nt = 0; nt < 16; nt++) {
        const int cb = nt * 8 + 2 * lr;
        *(__half2*)(Og + cb) =
            __floats2half2_rn(oacc[nt][0] * inv0, oacc[nt][1] * inv0);
        *(__half2*)(Og + (size_t)8 * DM + cb) =
            __floats2half2_rn(oacc[nt][2] * inv1, oacc[nt][3] * inv1);
    }
}

// ---------------------------------------------------------------------------
// Launch
// ---------------------------------------------------------------------------
extern "C" void kernel_launch(void* const* d_in, const int* in_sizes, int n_in,
                              void* d_out, int out_size)
{
    const float* hs   = (const float*)d_in[0];
    const float* cosb = (const float*)d_in[1];
    const float* sinb = (const float*)d_in[2];
    const float* Wqkv = (const float*)d_in[3];
    const float* Wout = (const float*)d_in[4];
    float* out = (float*)d_out;

    float*  qkv_ptr;
    __half *attn_ptr, *rA, *rWq, *rWo;
    cudaGetSymbolAddress((void**)&qkv_ptr,  g_qkv);
    cudaGetSymbolAddress((void**)&attn_ptr, g_attn);
    cudaGetSymbolAddress((void**)&rA,  g_rA);
    cudaGetSymbolAddress((void**)&rWq, g_rWq);
    cudaGetSymbolAddress((void**)&rWo, g_rWo);

    cudaFuncSetAttribute(hgemm_k, cudaFuncAttributeMaxDynamicSharedMemorySize,
                         HG_SMEM_BYTES);
    cudaFuncSetAttribute(fattn_k, cudaFuncAttributeMaxDynamicSharedMemorySize,
                         FA_SMEM_BYTES);

    // 0) fp16 conversion of activations; transpose+convert of weights
    cvt_k<<<592, 256>>>(hs, rA, (size_t)MROWS * DM / 4);
    tcvt_k<<<dim3(QKVD / 32, DM / 32), dim3(32, 8)>>>(Wqkv, rWq, DM, QKVD);
    tcvt_k<<<dim3(DM / 32, DM / 32),   dim3(32, 8)>>>(Wout, rWo, DM, DM);

    // 1) QKV projection (fp16 MMA, fp32 accum/out)
    hgemm_k<<<dim3(QKVD / 128, MROWS / 128), 256, HG_SMEM_BYTES>>>(
        rA, rWq, qkv_ptr, MROWS, QKVD, DM);

    // 2) RoPE + fp16 convert of Q/K/V
    rope16_k<<<MROWS, 256>>>(cosb, sinb);

    // 3) Causal GQA flash attention (fp16)
    fattn_k<<<dim3(SS / 128, NH, BB), 256, FA_SMEM_BYTES>>>();

    // 4) Output projection (fp16 MMA, fp32 out)
    hgemm_k<<<dim3(DM / 128, MROWS / 128), 256, HG_SMEM_BYTES>>>(
        attn_ptr, rWo, out, MROWS, DM, DM);
}